// round 12
// baseline (speedup 1.0000x reference)
#include <cuda_runtime.h>
#include <cuda_fp16.h>
#include <cstdint>

#define SEQ   512
#define BATCH 4
#define NROWS (BATCH * SEQ)
#define DEMB  768
#define DCAT  784
#define KPAD  832             // 13 chunks of 64 halves
#define KCHUNKS 13
#define VOCAB 50265
#define NPAD  50432           // 197 * 256
#define MSZ   (BATCH * SEQ * SEQ)

// chunked layouts (halves): A chunk = 128 rows x 64; B chunk = 256 x 64
#define ACH 8192
#define BCH 16384

__device__ float  g_M1 [MSZ];
__device__ float  g_M2 [MSZ];
__device__ float  g_M3 [MSZ];
__device__ float  g_M4 [MSZ];
__device__ float  g_M8 [MSZ];
__device__ float  g_M12[MSZ];
__device__ float  g_x[NROWS * DCAT];
__device__ __half g_xh[(size_t)(NROWS / 128) * KCHUNKS * ACH];
__device__ __half g_wt[(size_t)(NPAD / 256) * KCHUNKS * BCH];
__device__ int    g_mask_flags;

// ================= helpers =================
__device__ __forceinline__ uint32_t smem_u32(const void* p) {
    uint32_t a;
    asm("{ .reg .u64 t; cvta.to.shared.u64 t, %1; cvt.u32.u64 %0, t; }"
        : "=r"(a) : "l"(p));
    return a;
}
__device__ __host__ __forceinline__ uint32_t swz_half(int r, int kh) {
    return (uint32_t)(r * 64 + ((((kh >> 3) ^ r) & 7) << 3) + (kh & 7));
}
__device__ __forceinline__ void mbar_init(uint32_t a, uint32_t cnt) {
    asm volatile("mbarrier.init.shared.b64 [%0], %1;" :: "r"(a), "r"(cnt) : "memory");
}
__device__ __forceinline__ void mbar_expect_tx(uint32_t a, uint32_t bytes) {
    asm volatile("mbarrier.arrive.expect_tx.shared.b64 _, [%0], %1;"
                 :: "r"(a), "r"(bytes) : "memory");
}
__device__ __forceinline__ void mbar_arrive(uint32_t a) {
    asm volatile("mbarrier.arrive.shared.b64 _, [%0];" :: "r"(a) : "memory");
}
__device__ __forceinline__ void bulk_g2s(uint32_t dst, const void* src,
                                         uint32_t bytes, uint32_t mbar) {
    asm volatile(
        "cp.async.bulk.shared::cluster.global.mbarrier::complete_tx::bytes "
        "[%0], [%1], %2, [%3];"
        :: "r"(dst), "l"(src), "r"(bytes), "r"(mbar) : "memory");
}
__device__ __forceinline__ void mbar_wait(uint32_t a, uint32_t ph) {
    uint32_t done;
    asm volatile(
        "{\n\t.reg .pred p;\n\t"
        "mbarrier.try_wait.parity.acquire.cta.shared::cta.b64 p, [%1], %2;\n\t"
        "selp.b32 %0, 1, 0, p;\n\t}"
        : "=r"(done) : "r"(a), "r"(ph) : "memory");
    if (!done) {
        asm volatile(
            "{\n\t.reg .pred P1;\n\t"
            "WL_%=:\n\t"
            "mbarrier.try_wait.parity.acquire.cta.shared::cta.b64 P1, [%0], %1, 0x989680;\n\t"
            "@P1 bra.uni WD_%=;\n\t"
            "bra.uni WL_%=;\n\t"
            "WD_%=:\n\t}"
            :: "r"(a), "r"(ph) : "memory");
    }
}

// ================= mask dtype detection =================
__global__ void reset_flags_kernel() { g_mask_flags = 0; }

__global__ __launch_bounds__(256) void detect_mask_kernel(
    const uint4* __restrict__ p, int nvec)
{
    int fl = 0;
    for (int i = blockIdx.x * blockDim.x + threadIdx.x; i < nvec;
         i += gridDim.x * blockDim.x) {
        uint4 v = p[i];
        uint32_t any = v.x | v.y | v.z | v.w;
        if (any & 0xFEFEFEFEu) fl |= 2;
        else if (any & 0x01010100u) fl |= 1;
    }
    if (fl) atomicOr(&g_mask_flags, fl);
}

__device__ __forceinline__ int mask_fmt() {
    int f = g_mask_flags;
    return (f & 2) ? 2 : ((f & 1) ? 1 : 0);
}
__device__ __forceinline__ bool mask_at(const void* m, int fmt, long idx) {
    if (fmt == 0) return ((const int*)m)[idx] != 0;
    if (fmt == 1) return ((const unsigned char*)m)[idx] != 0;
    return ((const float*)m)[idx] != 0.0f;
}

// ================= W -> chunked swizzled fp16 =================
__global__ __launch_bounds__(256) void convert_w_kernel(
    const float* __restrict__ W, __half* __restrict__ Wt)
{
    __shared__ float t[32][33];
    int n0 = blockIdx.x * 32, k0 = blockIdx.y * 32;
    int tx = threadIdx.x & 31, ty = threadIdx.x >> 5;
    #pragma unroll
    for (int i = 0; i < 32; i += 8) {
        int k = k0 + ty + i, n = n0 + tx;
        t[ty + i][tx] = (k < DCAT && n < VOCAB) ? W[(size_t)k * VOCAB + n] : 0.0f;
    }
    __syncthreads();
    #pragma unroll
    for (int i = 0; i < 32; i += 8) {
        int n = n0 + ty + i, k = k0 + tx;
        int ntile = n >> 8, rr = n & 255;
        int kc = k >> 6, kh = k & 63;
        size_t base = ((size_t)ntile * KCHUNKS + kc) * BCH;
        Wt[base + swz_half(rr, kh)] = __float2half_rn(t[tx][ty + i]);
    }
}

// ================= x -> chunked swizzled fp16 =================
__global__ __launch_bounds__(256) void convert_x_kernel(
    const float* __restrict__ x, __half* __restrict__ xh)
{
    int i = blockIdx.x * 256 + threadIdx.x;
    if (i < NROWS * KPAD) {
        int row = i / KPAD, khg = i - row * KPAD;
        int mtile = row >> 7, r = row & 127;
        int kc = khg >> 6, kh = khg & 63;
        size_t base = ((size_t)mtile * KCHUNKS + kc) * ACH;
        float v = (khg < DCAT) ? x[(size_t)row * DCAT + khg] : 0.0f;
        xh[base + swz_half(r, kh)] = __float2half_rn(v);
    }
}

// ================= embedding gather + masked node average =================
__global__ __launch_bounds__(256) void embed_kernel(
    const int* __restrict__ code, const int* __restrict__ pos,
    const void* __restrict__ mask, const float* __restrict__ table,
    float* __restrict__ x)
{
    int row = blockIdx.x;
    int b = row >> 9;
    int tid = threadIdx.x;
    long xb = (long)row * DCAT;

    if (pos[row] != 0) {
        long co = (long)code[row] * DEMB;
        #pragma unroll
        for (int l = 0; l < 3; l++) x[xb + tid + l * 256] = table[co + tid + l * 256];
    } else {
        __shared__ int list[SEQ];
        __shared__ int cnt;
        if (tid == 0) cnt = 0;
        __syncthreads();
        int fmt = mask_fmt();
        for (int j = tid; j < SEQ; j += 256) {
            bool f = (pos[(b << 9) + j] >= 2) && mask_at(mask, fmt, (long)row * SEQ + j);
            if (f) { int k = atomicAdd(&cnt, 1); list[k] = code[(b << 9) + j]; }
        }
        __syncthreads();
        int n = cnt;
        float inv = 1.0f / ((float)n + 1e-10f);
        float a0 = 0.f, a1 = 0.f, a2 = 0.f;
        int jj = 0;
        for (; jj + 4 <= n; jj += 4) {
            const float* e0 = table + (long)list[jj] * DEMB;
            const float* e1 = table + (long)list[jj + 1] * DEMB;
            const float* e2 = table + (long)list[jj + 2] * DEMB;
            const float* e3 = table + (long)list[jj + 3] * DEMB;
            a0 += e0[tid] + e1[tid] + e2[tid] + e3[tid];
            a1 += e0[tid + 256] + e1[tid + 256] + e2[tid + 256] + e3[tid + 256];
            a2 += e0[tid + 512] + e1[tid + 512] + e2[tid + 512] + e3[tid + 512];
        }
        for (; jj < n; jj++) {
            const float* e0 = table + (long)list[jj] * DEMB;
            a0 += e0[tid]; a1 += e0[tid + 256]; a2 += e0[tid + 512];
        }
        x[xb + tid] = a0 * inv; x[xb + tid + 256] = a1 * inv; x[xb + tid + 512] = a2 * inv;
    }
}

// ================= M = D^-1 A =================
__global__ __launch_bounds__(128) void build_m_kernel(
    const void* __restrict__ mask, float* __restrict__ M1)
{
    int row = blockIdx.x;
    int i = row & (SEQ - 1);
    int tid = threadIdx.x;
    int fmt = mask_fmt();
    long base = (long)row * SEQ;
    __shared__ float red[128];

    float s = 0.f;
    for (int j = tid; j < SEQ; j += 128)
        s += (j == i) ? 1.0f : (mask_at(mask, fmt, base + j) ? 1.0f : 0.0f);
    red[tid] = s;
    __syncthreads();
    #pragma unroll
    for (int off = 64; off > 0; off >>= 1) {
        if (tid < off) red[tid] += red[tid + off];
        __syncthreads();
    }
    float inv = 1.0f / red[0];
    for (int j = tid; j < SEQ; j += 128) {
        float a = (j == i) ? 1.0f : (mask_at(mask, fmt, base + j) ? 1.0f : 0.0f);
        M1[base + j] = a * inv;
    }
}

__device__ __forceinline__ uint32_t f2tf32(float f) {
    uint32_t u;
    asm("cvt.rna.tf32.f32 %0, %1;" : "=r"(u) : "f"(f));
    return u;
}

// ================= power GEMM body (tf32 128x128) =================
__device__ __forceinline__ void gemm_tf32_body(
    const float* __restrict__ A, const float* __restrict__ B,
    float* __restrict__ C, int m0, int n0, int K)
{
    __shared__ float As[2][128][20];
    __shared__ float Bs[2][16][136];

    const int tid = threadIdx.x;
    const int lane = tid & 31, warp = tid >> 5;
    const int wm = (warp >> 2) * 64;
    const int wn = (warp & 3) * 32;
    const int g = lane >> 2, t4 = lane & 3;

    float acc[4][4][4];
    #pragma unroll
    for (int a = 0; a < 4; a++)
        #pragma unroll
        for (int bq = 0; bq < 4; bq++)
            #pragma unroll
            for (int c = 0; c < 4; c++) acc[a][bq][c] = 0.f;

    const int KT = K >> 4;
    float4 ra[2];
    float  rb[8];

    auto ldg_tiles = [&](int kt) {
        #pragma unroll
        for (int l = 0; l < 2; l++) {
            int idx = tid + l * 256;
            int ar = idx >> 2, ak = (idx & 3) << 2;
            ra[l] = *reinterpret_cast<const float4*>(
                A + (size_t)(m0 + ar) * SEQ + (kt * 16 + ak));
        }
        #pragma unroll
        for (int l = 0; l < 8; l++) {
            int idx = tid + l * 256;
            rb[l] = B[(size_t)(kt * 16 + (idx >> 7)) * SEQ + n0 + (idx & 127)];
        }
    };
    auto sts_tiles = [&](int buf) {
        #pragma unroll
        for (int l = 0; l < 2; l++) {
            int idx = tid + l * 256;
            int ar = idx >> 2, ak = (idx & 3) << 2;
            As[buf][ar][ak + 0] = __uint_as_float(f2tf32(ra[l].x));
            As[buf][ar][ak + 1] = __uint_as_float(f2tf32(ra[l].y));
            As[buf][ar][ak + 2] = __uint_as_float(f2tf32(ra[l].z));
            As[buf][ar][ak + 3] = __uint_as_float(f2tf32(ra[l].w));
        }
        #pragma unroll
        for (int l = 0; l < 8; l++) {
            int idx = tid + l * 256;
            Bs[buf][idx >> 7][idx & 127] = __uint_as_float(f2tf32(rb[l]));
        }
    };
    auto compute = [&](int buf) {
        #pragma unroll
        for (int ks = 0; ks < 2; ks++) {
            uint32_t af[4][4];
            int k = ks * 8 + t4;
            #pragma unroll
            for (int tm = 0; tm < 4; tm++) {
                int r = wm + tm * 16 + g;
                af[tm][0] = __float_as_uint(As[buf][r][k]);
                af[tm][1] = __float_as_uint(As[buf][r + 8][k]);
                af[tm][2] = __float_as_uint(As[buf][r][k + 4]);
                af[tm][3] = __float_as_uint(As[buf][r + 8][k + 4]);
            }
            uint32_t bf[4][2];
            #pragma unroll
            for (int tn = 0; tn < 4; tn++) {
                int c = wn + tn * 8 + g;
                bf[tn][0] = __float_as_uint(Bs[buf][k][c]);
                bf[tn][1] = __float_as_uint(Bs[buf][k + 4][c]);
            }
            #pragma unroll
            for (int tm = 0; tm < 4; tm++)
                #pragma unroll
                for (int tn = 0; tn < 4; tn++)
                    asm volatile(
                        "mma.sync.aligned.m16n8k8.row.col.f32.tf32.tf32.f32 "
                        "{%0,%1,%2,%3}, {%4,%5,%6,%7}, {%8,%9}, {%0,%1,%2,%3};\n"
                        : "+f"(acc[tm][tn][0]), "+f"(acc[tm][tn][1]),
                          "+f"(acc[tm][tn][2]), "+f"(acc[tm][tn][3])
                        : "r"(af[tm][0]), "r"(af[tm][1]),
                          "r"(af[tm][2]), "r"(af[tm][3]),
                          "r"(bf[tn][0]), "r"(bf[tn][1]));
        }
    };

    ldg_tiles(0);
    sts_tiles(0);
    __syncthreads();
    for (int kt = 0; kt < KT; kt++) {
        if (kt + 1 < KT) ldg_tiles(kt + 1);
        compute(kt & 1);
        if (kt + 1 < KT) sts_tiles((kt + 1) & 1);
        __syncthreads();
    }

    #pragma unroll
    for (int tm = 0; tm < 4; tm++) {
        int r = m0 + wm + tm * 16 + g;
        #pragma unroll
        for (int tn = 0; tn < 4; tn++) {
            int c = n0 + wn + tn * 8 + (t4 << 1);
            C[(size_t)r * SEQ + c]           = acc[tm][tn][0];
            C[(size_t)r * SEQ + c + 1]       = acc[tm][tn][1];
            C[(size_t)(r + 8) * SEQ + c]     = acc[tm][tn][2];
            C[(size_t)(r + 8) * SEQ + c + 1] = acc[tm][tn][3];
        }
    }
}

__global__ __launch_bounds__(256, 2) void gemm_tf32_kernel(
    const float* __restrict__ A, const float* __restrict__ B,
    float* __restrict__ C, int K, long strideM)
{
    gemm_tf32_body(A + blockIdx.z * strideM, B + blockIdx.z * strideM,
                   C + blockIdx.z * strideM, blockIdx.x * 128, blockIdx.y * 128, K);
}

__global__ __launch_bounds__(256, 2) void gemm_tf32_dual(
    const float* __restrict__ A,
    const float* __restrict__ B0, const float* __restrict__ B1,
    float* __restrict__ C0, float* __restrict__ C1,
    int K, long strideM)
{
    int z = blockIdx.z;
    int bz = z & 3;
    const float* B = (z < 4) ? B0 : B1;
    float*       C = (z < 4) ? C0 : C1;
    gemm_tf32_body(A + bz * strideM, B + bz * strideM, C + bz * strideM,
                   blockIdx.x * 128, blockIdx.y * 128, K);
}

// ================= final GEMM: fp16 mma, 512 threads, bulk pipeline =================
#define STG_BYTES (ACH * 2 + BCH * 2)   // 49152
#define NSTAGE 4
#define FSMEM (NSTAGE * STG_BYTES + 1024)

__global__ __launch_bounds__(512, 1) void gemm_final_fp16(
    const __half* __restrict__ A, const __half* __restrict__ B,
    float* __restrict__ C, const float* __restrict__ bias)
{
    extern __shared__ char dynsm[];
    __shared__ __align__(8) uint64_t s_full[NSTAGE];
    __shared__ __align__(8) uint64_t s_empty[NSTAGE];

    const int mt = blockIdx.x;
    const int nt = blockIdx.y;
    const int m0 = mt * 128;
    const int n0 = nt * 256;
    const int tid = threadIdx.x;
    const int lane = tid & 31, warp = tid >> 5;
    const int wm = (warp >> 2) * 32;     // 4 warp-rows of 32
    const int wn = (warp & 3) * 64;      // 4 warp-cols of 64
    const int g = lane >> 2, t4 = lane & 3;

    uint32_t raw_u = smem_u32(dynsm);
    uint32_t base_u = (raw_u + 1023u) & ~1023u;
    char* base_g = dynsm + (base_u - raw_u);

    const __half* Ach = A + (size_t)mt * KCHUNKS * ACH;
    const __half* Bch = B + (size_t)nt * KCHUNKS * BCH;

    uint32_t fullb[NSTAGE], emptyb[NSTAGE];
    #pragma unroll
    for (int s = 0; s < NSTAGE; s++) {
        fullb[s]  = smem_u32(&s_full[s]);
        emptyb[s] = smem_u32(&s_empty[s]);
    }

    if (tid == 0) {
        #pragma unroll
        for (int s = 0; s < NSTAGE; s++) {
            mbar_init(fullb[s], 1);
            mbar_init(emptyb[s], 16);
        }
    }
    __syncthreads();

    if (tid == 0) {
        #pragma unroll
        for (int s = 0; s < NSTAGE; s++) {
            mbar_expect_tx(fullb[s], STG_BYTES);
            bulk_g2s(base_u + s * STG_BYTES,           Ach + (size_t)s * ACH, ACH * 2, fullb[s]);
            bulk_g2s(base_u + s * STG_BYTES + ACH * 2, Bch + (size_t)s * BCH, BCH * 2, fullb[s]);
        }
    }

    float acc[2][8][4];
    #pragma unroll
    for (int a = 0; a < 2; a++)
        #pragma unroll
        for (int b = 0; b < 8; b++)
            #pragma unroll
            for (int c = 0; c < 4; c++) acc[a][b][c] = 0.f;

    int fph[NSTAGE] = {0, 0, 0, 0};
    int eph[NSTAGE] = {0, 0, 0, 0};

    for (int kc = 0; kc < KCHUNKS; kc++) {
        int s = kc & 3;
        mbar_wait(fullb[s], fph[s]);
        fph[s] ^= 1;

        const char* a0 = base_g + s * STG_BYTES;
        const char* b0 = a0 + ACH * 2;

        #pragma unroll
        for (int kk = 0; kk < 4; kk++) {
            int kh = kk * 16 + 2 * t4;
            uint32_t af[2][4];
            #pragma unroll
            for (int tm = 0; tm < 2; tm++) {
                int r = wm + tm * 16 + g;
                af[tm][0] = *(const uint32_t*)(a0 + swz_half(r,     kh)     * 2);
                af[tm][1] = *(const uint32_t*)(a0 + swz_half(r + 8, kh)     * 2);
                af[tm][2] = *(const uint32_t*)(a0 + swz_half(r,     kh + 8) * 2);
                af[tm][3] = *(const uint32_t*)(a0 + swz_half(r + 8, kh + 8) * 2);
            }
            uint32_t bf[8][2];
            #pragma unroll
            for (int tn = 0; tn < 8; tn++) {
                int c = wn + tn * 8 + g;
                bf[tn][0] = *(const uint32_t*)(b0 + swz_half(c, kh)     * 2);
                bf[tn][1] = *(const uint32_t*)(b0 + swz_half(c, kh + 8) * 2);
            }
            #pragma unroll
            for (int tm = 0; tm < 2; tm++)
                #pragma unroll
                for (int tn = 0; tn < 8; tn++)
                    asm volatile(
                        "mma.sync.aligned.m16n8k16.row.col.f32.f16.f16.f32 "
                        "{%0,%1,%2,%3}, {%4,%5,%6,%7}, {%8,%9}, {%0,%1,%2,%3};\n"
                        : "+f"(acc[tm][tn][0]), "+f"(acc[tm][tn][1]),
                          "+f"(acc[tm][tn][2]), "+f"(acc[tm][tn][3])
                        : "r"(af[tm][0]), "r"(af[tm][1]),
                          "r"(af[tm][2]), "r"(af[tm][3]),
                          "r"(bf[tn][0]), "r"(bf[tn][1]));
        }

        __syncwarp();
        if (lane == 0) mbar_arrive(emptyb[s]);

        if (tid == 0) {
            int nkc = kc + NSTAGE;
            if (nkc < KCHUNKS) {
                mbar_wait(emptyb[s], eph[s]);
                eph[s] ^= 1;
                mbar_expect_tx(fullb[s], STG_BYTES);
                bulk_g2s(base_u + s * STG_BYTES,           Ach + (size_t)nkc * ACH, ACH * 2, fullb[s]);
                bulk_g2s(base_u + s * STG_BYTES + ACH * 2, Bch + (size_t)nkc * BCH, BCH * 2, fullb[s]);
            }
        }
    }

    // ---- epilogue: scalar stores (VOCAB odd -> rows alternate 8B alignment) ----
    bool interior = (n0 + 256 <= VOCAB);
    #pragma unroll
    for (int tm = 0; tm < 2; tm++) {
        int r = m0 + wm + tm * 16 + g;
        float* C0 = C + (size_t)r * VOCAB;
        float* C1 = C + (size_t)(r + 8) * VOCAB;
        #pragma unroll
        for (int tn = 0; tn < 8; tn++) {
            int c = n0 + wn + tn * 8 + (t4 << 1);
            if (interior) {
                float b0 = bias[c], b1 = bias[c + 1];
                C0[c]     = acc[tm][tn][0] + b0;
                C0[c + 1] = acc[tm][tn][1] + b1;
                C1[c]     = acc[tm][tn][2] + b0;
                C1[c + 1] = acc[tm][tn][3] + b1;
            } else {
                if (c < VOCAB) {
                    float bv = bias[c];
                    C0[c] = acc[tm][tn][0] + bv;
                    C1[c] = acc[tm][tn][2] + bv;
                }
                if (c + 1 < VOCAB) {
                    float bv = bias[c + 1];
                    C0[c + 1] = acc[tm][tn][1] + bv;
                    C1[c + 1] = acc[tm][tn][3] + bv;
                }
            }
        }
    }
}

// ================= diag(M^k) k=1..16 =================
__global__ __launch_bounds__(128) void diag_pe_kernel(
    const float* __restrict__ M1, const float* __restrict__ M2,
    const float* __restrict__ M3, const float* __restrict__ M4,
    const float* __restrict__ M8, const float* __restrict__ M12,
    float* __restrict__ x)
{
    int row = blockIdx.x;
    int b = row >> 9, i = row & (SEQ - 1);
    int tid = threadIdx.x, lane = tid & 31, warp = tid >> 5;
    long base = (long)row * SEQ;
    long mbq  = (long)b * SEQ * SEQ;

    __shared__ float rws[4][SEQ];
    __shared__ float cls[3][SEQ];
    __shared__ float wred[10][4];

    for (int j = tid; j < SEQ; j += 128) {
        rws[0][j] = M1[base + j];
        rws[1][j] = M2[base + j];
        rws[2][j] = M3[base + j];
        rws[3][j] = M4[base + j];
        cls[0][j] = M4 [mbq + (long)j * SEQ + i];
        cls[1][j] = M8 [mbq + (long)j * SEQ + i];
        cls[2][j] = M12[mbq + (long)j * SEQ + i];
    }
    __syncthreads();

    float part[10];
    #pragma unroll
    for (int p = 0; p < 10; p++) part[p] = 0.f;
    for (int j = tid; j < SEQ; j += 128) {
        float a1 = rws[0][j], a2 = rws[1][j], a3 = rws[2][j], a4 = rws[3][j];
        float c4 = cls[0][j], c8 = cls[1][j], c12 = cls[2][j];
        part[0] += a1 * c4;   part[1] += a2 * c4;   part[2] += a3 * c4;
        part[3] += a1 * c8;   part[4] += a2 * c8;   part[5] += a3 * c8;
        part[6] += a1 * c12;  part[7] += a2 * c12;  part[8] += a3 * c12;
        part[9] += a4 * c12;
    }
    #pragma unroll
    for (int p = 0; p < 10; p++) {
        float v = part[p];
        #pragma unroll
        for (int off = 16; off > 0; off >>= 1) v += __shfl_down_sync(0xffffffffu, v, off);
        if (lane == 0) wred[p][warp] = v;
    }
    __syncthreads();

    long xb = (long)row * DCAT + DEMB;
    if (tid < 10) {
        const int slot[10] = {4, 5, 6, 8, 9, 10, 12, 13, 14, 15};
        x[xb + slot[tid]] = wred[tid][0] + wred[tid][1] + wred[tid][2] + wred[tid][3];
    }
    if (tid == 0) {
        x[xb + 0]  = rws[0][i];
        x[xb + 1]  = rws[1][i];
        x[xb + 2]  = rws[2][i];
        x[xb + 3]  = rws[3][i];
        x[xb + 7]  = cls[1][i];
        x[xb + 11] = cls[2][i];
    }
}

extern "C" void kernel_launch(void* const* d_in, const int* in_sizes, int n_in,
                              void* d_out, int out_size)
{
    const int*   code  = (const int*)d_in[0];
    const int*   pos   = (const int*)d_in[1];
    const void*  mask  = d_in[2];
    const float* table = (const float*)d_in[3];
    const float* W     = (const float*)d_in[4];
    const float* bias  = (const float*)d_in[5];
    float* out = (float*)d_out;

    float *pM1, *pM2, *pM3, *pM4, *pM8, *pM12, *px;
    __half *pxh, *pwt;
    cudaGetSymbolAddress((void**)&pM1,  g_M1);
    cudaGetSymbolAddress((void**)&pM2,  g_M2);
    cudaGetSymbolAddress((void**)&pM3,  g_M3);
    cudaGetSymbolAddress((void**)&pM4,  g_M4);
    cudaGetSymbolAddress((void**)&pM8,  g_M8);
    cudaGetSymbolAddress((void**)&pM12, g_M12);
    cudaGetSymbolAddress((void**)&px,   g_x);
    cudaGetSymbolAddress((void**)&pxh,  g_xh);
    cudaGetSymbolAddress((void**)&pwt,  g_wt);

    const long MS = (long)SEQ * SEQ;

    cudaFuncSetAttribute(gemm_final_fp16,
                         cudaFuncAttributeMaxDynamicSharedMemorySize, FSMEM);

    reset_flags_kernel<<<1, 1>>>();
    detect_mask_kernel<<<64, 256>>>((const uint4*)mask, in_sizes[2] / 16);

    dim3 gW(NPAD / 32, (KPAD + 31) / 32);
    convert_w_kernel<<<gW, 256>>>(W, pwt);

    embed_kernel<<<NROWS, 256>>>(code, pos, mask, table, px);
    build_m_kernel<<<NROWS, 128>>>(mask, pM1);

    dim3 gP(SEQ / 128, SEQ / 128, BATCH);
    dim3 gD(SEQ / 128, SEQ / 128, 2 * BATCH);
    gemm_tf32_kernel<<<gP, 256>>>(pM1, pM1, pM2, SEQ, MS);
    gemm_tf32_dual<<<gD, 256>>>(pM2, pM1, pM2, pM3, pM4, SEQ, MS);  // M3=M2*M1, M4=M2*M2
    gemm_tf32_kernel<<<gP, 256>>>(pM4, pM4, pM8,  SEQ, MS);
    gemm_tf32_kernel<<<gP, 256>>>(pM8, pM4, pM12, SEQ, MS);

    diag_pe_kernel<<<NROWS, 128>>>(pM1, pM2, pM3, pM4, pM8, pM12, px);

    convert_x_kernel<<<(NROWS * KPAD + 255) / 256, 256>>>(px, pxh);

    dim3 gF(NROWS / 128, NPAD / 256, 1);   // (16, 197)
    gemm_final_fp16<<<gF, 512, FSMEM>>>(pxh, pwt, out, bias);
}

// round 13
// speedup vs baseline: 1.1168x; 1.1168x over previous
#include <cuda_runtime.h>
#include <cuda_fp16.h>
#include <cstdint>

#define SEQ   512
#define BATCH 4
#define NROWS (BATCH * SEQ)
#define DEMB  768
#define DCAT  784
#define KPAD  832             // 13 chunks of 64 halves
#define KCHUNKS 13
#define VOCAB 50265
#define NPAD  50432           // 394 * 128
#define MSZ   (BATCH * SEQ * SEQ)

// chunked layouts (halves): A chunk = 128 rows x 64; B chunk = 128 rows x 64
#define ACH 8192
#define BCH 8192

__device__ float  g_M1 [MSZ];
__device__ float  g_M2 [MSZ];
__device__ float  g_M3 [MSZ];
__device__ float  g_M4 [MSZ];
__device__ float  g_M8 [MSZ];
__device__ float  g_M12[MSZ];
__device__ float  g_x[NROWS * DCAT];
__device__ __half g_xh[(size_t)(NROWS / 128) * KCHUNKS * ACH];
__device__ __half g_wt[(size_t)(NPAD / 128) * KCHUNKS * BCH];
__device__ int    g_mask_flags;

// ================= helpers =================
__device__ __forceinline__ uint32_t smem_u32(const void* p) {
    uint32_t a;
    asm("{ .reg .u64 t; cvta.to.shared.u64 t, %1; cvt.u32.u64 %0, t; }"
        : "=r"(a) : "l"(p));
    return a;
}
__device__ __host__ __forceinline__ uint32_t swz_half(int r, int kh) {
    return (uint32_t)(r * 64 + ((((kh >> 3) ^ r) & 7) << 3) + (kh & 7));
}
__device__ __forceinline__ void mbar_init(uint32_t a, uint32_t cnt) {
    asm volatile("mbarrier.init.shared.b64 [%0], %1;" :: "r"(a), "r"(cnt) : "memory");
}
__device__ __forceinline__ void mbar_expect_tx(uint32_t a, uint32_t bytes) {
    asm volatile("mbarrier.arrive.expect_tx.shared.b64 _, [%0], %1;"
                 :: "r"(a), "r"(bytes) : "memory");
}
__device__ __forceinline__ void mbar_arrive(uint32_t a) {
    asm volatile("mbarrier.arrive.shared.b64 _, [%0];" :: "r"(a) : "memory");
}
__device__ __forceinline__ void bulk_g2s(uint32_t dst, const void* src,
                                         uint32_t bytes, uint32_t mbar) {
    asm volatile(
        "cp.async.bulk.shared::cluster.global.mbarrier::complete_tx::bytes "
        "[%0], [%1], %2, [%3];"
        :: "r"(dst), "l"(src), "r"(bytes), "r"(mbar) : "memory");
}
__device__ __forceinline__ void mbar_wait(uint32_t a, uint32_t ph) {
    uint32_t done;
    asm volatile(
        "{\n\t.reg .pred p;\n\t"
        "mbarrier.try_wait.parity.acquire.cta.shared::cta.b64 p, [%1], %2;\n\t"
        "selp.b32 %0, 1, 0, p;\n\t}"
        : "=r"(done) : "r"(a), "r"(ph) : "memory");
    if (!done) {
        asm volatile(
            "{\n\t.reg .pred P1;\n\t"
            "WL_%=:\n\t"
            "mbarrier.try_wait.parity.acquire.cta.shared::cta.b64 P1, [%0], %1, 0x989680;\n\t"
            "@P1 bra.uni WD_%=;\n\t"
            "bra.uni WL_%=;\n\t"
            "WD_%=:\n\t}"
            :: "r"(a), "r"(ph) : "memory");
    }
}

// ================= mask dtype detection =================
__global__ void reset_flags_kernel() { g_mask_flags = 0; }

__global__ __launch_bounds__(256) void detect_mask_kernel(
    const uint4* __restrict__ p, int nvec)
{
    int fl = 0;
    for (int i = blockIdx.x * blockDim.x + threadIdx.x; i < nvec;
         i += gridDim.x * blockDim.x) {
        uint4 v = p[i];
        uint32_t any = v.x | v.y | v.z | v.w;
        if (any & 0xFEFEFEFEu) fl |= 2;
        else if (any & 0x01010100u) fl |= 1;
    }
    if (fl) atomicOr(&g_mask_flags, fl);
}

__device__ __forceinline__ int mask_fmt() {
    int f = g_mask_flags;
    return (f & 2) ? 2 : ((f & 1) ? 1 : 0);
}
__device__ __forceinline__ bool mask_at(const void* m, int fmt, long idx) {
    if (fmt == 0) return ((const int*)m)[idx] != 0;
    if (fmt == 1) return ((const unsigned char*)m)[idx] != 0;
    return ((const float*)m)[idx] != 0.0f;
}

// ================= W -> chunked swizzled fp16 (128-row tiles) =================
__global__ __launch_bounds__(256) void convert_w_kernel(
    const float* __restrict__ W, __half* __restrict__ Wt)
{
    __shared__ float t[32][33];
    int n0 = blockIdx.x * 32, k0 = blockIdx.y * 32;
    int tx = threadIdx.x & 31, ty = threadIdx.x >> 5;
    #pragma unroll
    for (int i = 0; i < 32; i += 8) {
        int k = k0 + ty + i, n = n0 + tx;
        t[ty + i][tx] = (k < DCAT && n < VOCAB) ? W[(size_t)k * VOCAB + n] : 0.0f;
    }
    __syncthreads();
    #pragma unroll
    for (int i = 0; i < 32; i += 8) {
        int n = n0 + ty + i, k = k0 + tx;
        int ntile = n >> 7, rr = n & 127;
        int kc = k >> 6, kh = k & 63;
        size_t base = ((size_t)ntile * KCHUNKS + kc) * BCH;
        Wt[base + swz_half(rr, kh)] = __float2half_rn(t[tx][ty + i]);
    }
}

// ================= x -> chunked swizzled fp16 =================
__global__ __launch_bounds__(256) void convert_x_kernel(
    const float* __restrict__ x, __half* __restrict__ xh)
{
    int i = blockIdx.x * 256 + threadIdx.x;
    if (i < NROWS * KPAD) {
        int row = i / KPAD, khg = i - row * KPAD;
        int mtile = row >> 7, r = row & 127;
        int kc = khg >> 6, kh = khg & 63;
        size_t base = ((size_t)mtile * KCHUNKS + kc) * ACH;
        float v = (khg < DCAT) ? x[(size_t)row * DCAT + khg] : 0.0f;
        xh[base + swz_half(r, kh)] = __float2half_rn(v);
    }
}

// ================= embedding gather + masked node average =================
__global__ __launch_bounds__(256) void embed_kernel(
    const int* __restrict__ code, const int* __restrict__ pos,
    const void* __restrict__ mask, const float* __restrict__ table,
    float* __restrict__ x)
{
    int row = blockIdx.x;
    int b = row >> 9;
    int tid = threadIdx.x;
    long xb = (long)row * DCAT;

    if (pos[row] != 0) {
        long co = (long)code[row] * DEMB;
        #pragma unroll
        for (int l = 0; l < 3; l++) x[xb + tid + l * 256] = table[co + tid + l * 256];
    } else {
        __shared__ int list[SEQ];
        __shared__ int cnt;
        if (tid == 0) cnt = 0;
        __syncthreads();
        int fmt = mask_fmt();
        for (int j = tid; j < SEQ; j += 256) {
            bool f = (pos[(b << 9) + j] >= 2) && mask_at(mask, fmt, (long)row * SEQ + j);
            if (f) { int k = atomicAdd(&cnt, 1); list[k] = code[(b << 9) + j]; }
        }
        __syncthreads();
        int n = cnt;
        float inv = 1.0f / ((float)n + 1e-10f);
        float a0 = 0.f, a1 = 0.f, a2 = 0.f;
        int jj = 0;
        for (; jj + 4 <= n; jj += 4) {
            const float* e0 = table + (long)list[jj] * DEMB;
            const float* e1 = table + (long)list[jj + 1] * DEMB;
            const float* e2 = table + (long)list[jj + 2] * DEMB;
            const float* e3 = table + (long)list[jj + 3] * DEMB;
            a0 += e0[tid] + e1[tid] + e2[tid] + e3[tid];
            a1 += e0[tid + 256] + e1[tid + 256] + e2[tid + 256] + e3[tid + 256];
            a2 += e0[tid + 512] + e1[tid + 512] + e2[tid + 512] + e3[tid + 512];
        }
        for (; jj < n; jj++) {
            const float* e0 = table + (long)list[jj] * DEMB;
            a0 += e0[tid]; a1 += e0[tid + 256]; a2 += e0[tid + 512];
        }
        x[xb + tid] = a0 * inv; x[xb + tid + 256] = a1 * inv; x[xb + tid + 512] = a2 * inv;
    }
}

// ================= M = D^-1 A =================
__global__ __launch_bounds__(128) void build_m_kernel(
    const void* __restrict__ mask, float* __restrict__ M1)
{
    int row = blockIdx.x;
    int i = row & (SEQ - 1);
    int tid = threadIdx.x;
    int fmt = mask_fmt();
    long base = (long)row * SEQ;
    __shared__ float red[128];

    float s = 0.f;
    for (int j = tid; j < SEQ; j += 128)
        s += (j == i) ? 1.0f : (mask_at(mask, fmt, base + j) ? 1.0f : 0.0f);
    red[tid] = s;
    __syncthreads();
    #pragma unroll
    for (int off = 64; off > 0; off >>= 1) {
        if (tid < off) red[tid] += red[tid + off];
        __syncthreads();
    }
    float inv = 1.0f / red[0];
    for (int j = tid; j < SEQ; j += 128) {
        float a = (j == i) ? 1.0f : (mask_at(mask, fmt, base + j) ? 1.0f : 0.0f);
        M1[base + j] = a * inv;
    }
}

__device__ __forceinline__ uint32_t f2tf32(float f) {
    uint32_t u;
    asm("cvt.rna.tf32.f32 %0, %1;" : "=r"(u) : "f"(f));
    return u;
}

// ================= power GEMM body (tf32 128x128) =================
__device__ __forceinline__ void gemm_tf32_body(
    const float* __restrict__ A, const float* __restrict__ B,
    float* __restrict__ C, int m0, int n0, int K)
{
    __shared__ float As[2][128][20];
    __shared__ float Bs[2][16][136];

    const int tid = threadIdx.x;
    const int lane = tid & 31, warp = tid >> 5;
    const int wm = (warp >> 2) * 64;
    const int wn = (warp & 3) * 32;
    const int g = lane >> 2, t4 = lane & 3;

    float acc[4][4][4];
    #pragma unroll
    for (int a = 0; a < 4; a++)
        #pragma unroll
        for (int bq = 0; bq < 4; bq++)
            #pragma unroll
            for (int c = 0; c < 4; c++) acc[a][bq][c] = 0.f;

    const int KT = K >> 4;
    float4 ra[2];
    float  rb[8];

    auto ldg_tiles = [&](int kt) {
        #pragma unroll
        for (int l = 0; l < 2; l++) {
            int idx = tid + l * 256;
            int ar = idx >> 2, ak = (idx & 3) << 2;
            ra[l] = *reinterpret_cast<const float4*>(
                A + (size_t)(m0 + ar) * SEQ + (kt * 16 + ak));
        }
        #pragma unroll
        for (int l = 0; l < 8; l++) {
            int idx = tid + l * 256;
            rb[l] = B[(size_t)(kt * 16 + (idx >> 7)) * SEQ + n0 + (idx & 127)];
        }
    };
    auto sts_tiles = [&](int buf) {
        #pragma unroll
        for (int l = 0; l < 2; l++) {
            int idx = tid + l * 256;
            int ar = idx >> 2, ak = (idx & 3) << 2;
            As[buf][ar][ak + 0] = __uint_as_float(f2tf32(ra[l].x));
            As[buf][ar][ak + 1] = __uint_as_float(f2tf32(ra[l].y));
            As[buf][ar][ak + 2] = __uint_as_float(f2tf32(ra[l].z));
            As[buf][ar][ak + 3] = __uint_as_float(f2tf32(ra[l].w));
        }
        #pragma unroll
        for (int l = 0; l < 8; l++) {
            int idx = tid + l * 256;
            Bs[buf][idx >> 7][idx & 127] = __uint_as_float(f2tf32(rb[l]));
        }
    };
    auto compute = [&](int buf) {
        #pragma unroll
        for (int ks = 0; ks < 2; ks++) {
            uint32_t af[4][4];
            int k = ks * 8 + t4;
            #pragma unroll
            for (int tm = 0; tm < 4; tm++) {
                int r = wm + tm * 16 + g;
                af[tm][0] = __float_as_uint(As[buf][r][k]);
                af[tm][1] = __float_as_uint(As[buf][r + 8][k]);
                af[tm][2] = __float_as_uint(As[buf][r][k + 4]);
                af[tm][3] = __float_as_uint(As[buf][r + 8][k + 4]);
            }
            uint32_t bf[4][2];
            #pragma unroll
            for (int tn = 0; tn < 4; tn++) {
                int c = wn + tn * 8 + g;
                bf[tn][0] = __float_as_uint(Bs[buf][k][c]);
                bf[tn][1] = __float_as_uint(Bs[buf][k + 4][c]);
            }
            #pragma unroll
            for (int tm = 0; tm < 4; tm++)
                #pragma unroll
                for (int tn = 0; tn < 4; tn++)
                    asm volatile(
                        "mma.sync.aligned.m16n8k8.row.col.f32.tf32.tf32.f32 "
                        "{%0,%1,%2,%3}, {%4,%5,%6,%7}, {%8,%9}, {%0,%1,%2,%3};\n"
                        : "+f"(acc[tm][tn][0]), "+f"(acc[tm][tn][1]),
                          "+f"(acc[tm][tn][2]), "+f"(acc[tm][tn][3])
                        : "r"(af[tm][0]), "r"(af[tm][1]),
                          "r"(af[tm][2]), "r"(af[tm][3]),
                          "r"(bf[tn][0]), "r"(bf[tn][1]));
        }
    };

    ldg_tiles(0);
    sts_tiles(0);
    __syncthreads();
    for (int kt = 0; kt < KT; kt++) {
        if (kt + 1 < KT) ldg_tiles(kt + 1);
        compute(kt & 1);
        if (kt + 1 < KT) sts_tiles((kt + 1) & 1);
        __syncthreads();
    }

    #pragma unroll
    for (int tm = 0; tm < 4; tm++) {
        int r = m0 + wm + tm * 16 + g;
        #pragma unroll
        for (int tn = 0; tn < 4; tn++) {
            int c = n0 + wn + tn * 8 + (t4 << 1);
            C[(size_t)r * SEQ + c]           = acc[tm][tn][0];
            C[(size_t)r * SEQ + c + 1]       = acc[tm][tn][1];
            C[(size_t)(r + 8) * SEQ + c]     = acc[tm][tn][2];
            C[(size_t)(r + 8) * SEQ + c + 1] = acc[tm][tn][3];
        }
    }
}

__global__ __launch_bounds__(256, 2) void gemm_tf32_kernel(
    const float* __restrict__ A, const float* __restrict__ B,
    float* __restrict__ C, int K, long strideM)
{
    gemm_tf32_body(A + blockIdx.z * strideM, B + blockIdx.z * strideM,
                   C + blockIdx.z * strideM, blockIdx.x * 128, blockIdx.y * 128, K);
}

__global__ __launch_bounds__(256, 2) void gemm_tf32_dual(
    const float* __restrict__ A,
    const float* __restrict__ B0, const float* __restrict__ B1,
    float* __restrict__ C0, float* __restrict__ C1,
    int K, long strideM)
{
    int z = blockIdx.z;
    int bz = z & 3;
    const float* B = (z < 4) ? B0 : B1;
    float*       C = (z < 4) ? C0 : C1;
    gemm_tf32_body(A + bz * strideM, B + bz * strideM, C + bz * strideM,
                   blockIdx.x * 128, blockIdx.y * 128, K);
}

// ================= final GEMM: fp16 mma, 128x128 tile, 2 CTAs/SM =================
#define STG_BYTES (ACH * 2 + BCH * 2)   // 32768
#define NSTAGE 3
#define FSMEM (NSTAGE * STG_BYTES + 1024)

__global__ __launch_bounds__(256, 2) void gemm_final_fp16(
    const __half* __restrict__ A, const __half* __restrict__ B,
    float* __restrict__ C, const float* __restrict__ bias)
{
    extern __shared__ char dynsm[];
    __shared__ __align__(8) uint64_t s_full[NSTAGE];
    __shared__ __align__(8) uint64_t s_empty[NSTAGE];

    const int mt = blockIdx.x;
    const int nt = blockIdx.y;
    const int m0 = mt * 128;
    const int n0 = nt * 128;
    const int tid = threadIdx.x;
    const int lane = tid & 31, warp = tid >> 5;
    const int wm = (warp >> 2) * 64;     // 2 warp-rows of 64
    const int wn = (warp & 3) * 32;      // 4 warp-cols of 32
    const int g = lane >> 2, t4 = lane & 3;

    uint32_t raw_u = smem_u32(dynsm);
    uint32_t base_u = (raw_u + 1023u) & ~1023u;
    char* base_g = dynsm + (base_u - raw_u);

    const __half* Ach = A + (size_t)mt * KCHUNKS * ACH;
    const __half* Bch = B + (size_t)nt * KCHUNKS * BCH;

    uint32_t fullb[NSTAGE], emptyb[NSTAGE];
    #pragma unroll
    for (int s = 0; s < NSTAGE; s++) {
        fullb[s]  = smem_u32(&s_full[s]);
        emptyb[s] = smem_u32(&s_empty[s]);
    }

    if (tid == 0) {
        #pragma unroll
        for (int s = 0; s < NSTAGE; s++) {
            mbar_init(fullb[s], 1);
            mbar_init(emptyb[s], 8);
        }
    }
    __syncthreads();

    if (tid == 0) {
        #pragma unroll
        for (int s = 0; s < NSTAGE; s++) {
            mbar_expect_tx(fullb[s], STG_BYTES);
            bulk_g2s(base_u + s * STG_BYTES,           Ach + (size_t)s * ACH, ACH * 2, fullb[s]);
            bulk_g2s(base_u + s * STG_BYTES + ACH * 2, Bch + (size_t)s * BCH, BCH * 2, fullb[s]);
        }
    }

    float acc[4][4][4];
    #pragma unroll
    for (int a = 0; a < 4; a++)
        #pragma unroll
        for (int b = 0; b < 4; b++)
            #pragma unroll
            for (int c = 0; c < 4; c++) acc[a][b][c] = 0.f;

    int fph[NSTAGE] = {0, 0, 0};
    int eph[NSTAGE] = {0, 0, 0};

    for (int kc = 0; kc < KCHUNKS; kc++) {
        int s = kc % NSTAGE;
        mbar_wait(fullb[s], fph[s]);
        fph[s] ^= 1;

        const char* a0 = base_g + s * STG_BYTES;
        const char* b0 = a0 + ACH * 2;

        #pragma unroll
        for (int kk = 0; kk < 4; kk++) {
            int kh = kk * 16 + 2 * t4;
            uint32_t af[4][4];
            #pragma unroll
            for (int tm = 0; tm < 4; tm++) {
                int r = wm + tm * 16 + g;
                af[tm][0] = *(const uint32_t*)(a0 + swz_half(r,     kh)     * 2);
                af[tm][1] = *(const uint32_t*)(a0 + swz_half(r + 8, kh)     * 2);
                af[tm][2] = *(const uint32_t*)(a0 + swz_half(r,     kh + 8) * 2);
                af[tm][3] = *(const uint32_t*)(a0 + swz_half(r + 8, kh + 8) * 2);
            }
            uint32_t bf[4][2];
            #pragma unroll
            for (int tn = 0; tn < 4; tn++) {
                int c = wn + tn * 8 + g;
                bf[tn][0] = *(const uint32_t*)(b0 + swz_half(c, kh)     * 2);
                bf[tn][1] = *(const uint32_t*)(b0 + swz_half(c, kh + 8) * 2);
            }
            #pragma unroll
            for (int tm = 0; tm < 4; tm++)
                #pragma unroll
                for (int tn = 0; tn < 4; tn++)
                    asm volatile(
                        "mma.sync.aligned.m16n8k16.row.col.f32.f16.f16.f32 "
                        "{%0,%1,%2,%3}, {%4,%5,%6,%7}, {%8,%9}, {%0,%1,%2,%3};\n"
                        : "+f"(acc[tm][tn][0]), "+f"(acc[tm][tn][1]),
                          "+f"(acc[tm][tn][2]), "+f"(acc[tm][tn][3])
                        : "r"(af[tm][0]), "r"(af[tm][1]),
                          "r"(af[tm][2]), "r"(af[tm][3]),
                          "r"(bf[tn][0]), "r"(bf[tn][1]));
        }

        __syncwarp();
        if (lane == 0) mbar_arrive(emptyb[s]);

        if (tid == 0) {
            int nkc = kc + NSTAGE;
            if (nkc < KCHUNKS) {
                mbar_wait(emptyb[s], eph[s]);
                eph[s] ^= 1;
                mbar_expect_tx(fullb[s], STG_BYTES);
                bulk_g2s(base_u + s * STG_BYTES,           Ach + (size_t)nkc * ACH, ACH * 2, fullb[s]);
                bulk_g2s(base_u + s * STG_BYTES + ACH * 2, Bch + (size_t)nkc * BCH, BCH * 2, fullb[s]);
            }
        }
    }

    // ---- epilogue: scalar stores (VOCAB odd pitch) ----
    bool interior = (n0 + 128 <= VOCAB);
    #pragma unroll
    for (int tm = 0; tm < 4; tm++) {
        int r = m0 + wm + tm * 16 + g;
        float* C0 = C + (size_t)r * VOCAB;
        float* C1 = C + (size_t)(r + 8) * VOCAB;
        #pragma unroll
        for (int tn = 0; tn < 4; tn++) {
            int c = n0 + wn + tn * 8 + (t4 << 1);
            if (interior) {
                float b0 = bias[c], b1 = bias[c + 1];
                C0[c]     = acc[tm][tn][0] + b0;
                C0[c + 1] = acc[tm][tn][1] + b1;
                C1[c]     = acc[tm][tn][2] + b0;
                C1[c + 1] = acc[tm][tn][3] + b1;
            } else {
                if (c < VOCAB) {
                    float bv = bias[c];
                    C0[c] = acc[tm][tn][0] + bv;
                    C1[c] = acc[tm][tn][2] + bv;
                }
                if (c + 1 < VOCAB) {
                    float bv = bias[c + 1];
                    C0[c + 1] = acc[tm][tn][1] + bv;
                    C1[c + 1] = acc[tm][tn][3] + bv;
                }
            }
        }
    }
}

// ================= diag(M^k) k=1..16 =================
__global__ __launch_bounds__(128) void diag_pe_kernel(
    const float* __restrict__ M1, const float* __restrict__ M2,
    const float* __restrict__ M3, const float* __restrict__ M4,
    const float* __restrict__ M8, const float* __restrict__ M12,
    float* __restrict__ x)
{
    int row = blockIdx.x;
    int b = row >> 9, i = row & (SEQ - 1);
    int tid = threadIdx.x, lane = tid & 31, warp = tid >> 5;
    long base = (long)row * SEQ;
    long mbq  = (long)b * SEQ * SEQ;

    __shared__ float rws[4][SEQ];
    __shared__ float cls[3][SEQ];
    __shared__ float wred[10][4];

    for (int j = tid; j < SEQ; j += 128) {
        rws[0][j] = M1[base + j];
        rws[1][j] = M2[base + j];
        rws[2][j] = M3[base + j];
        rws[3][j] = M4[base + j];
        cls[0][j] = M4 [mbq + (long)j * SEQ + i];
        cls[1][j] = M8 [mbq + (long)j * SEQ + i];
        cls[2][j] = M12[mbq + (long)j * SEQ + i];
    }
    __syncthreads();

    float part[10];
    #pragma unroll
    for (int p = 0; p < 10; p++) part[p] = 0.f;
    for (int j = tid; j < SEQ; j += 128) {
        float a1 = rws[0][j], a2 = rws[1][j], a3 = rws[2][j], a4 = rws[3][j];
        float c4 = cls[0][j], c8 = cls[1][j], c12 = cls[2][j];
        part[0] += a1 * c4;   part[1] += a2 * c4;   part[2] += a3 * c4;
        part[3] += a1 * c8;   part[4] += a2 * c8;   part[5] += a3 * c8;
        part[6] += a1 * c12;  part[7] += a2 * c12;  part[8] += a3 * c12;
        part[9] += a4 * c12;
    }
    #pragma unroll
    for (int p = 0; p < 10; p++) {
        float v = part[p];
        #pragma unroll
        for (int off = 16; off > 0; off >>= 1) v += __shfl_down_sync(0xffffffffu, v, off);
        if (lane == 0) wred[p][warp] = v;
    }
    __syncthreads();

    long xb = (long)row * DCAT + DEMB;
    if (tid < 10) {
        const int slot[10] = {4, 5, 6, 8, 9, 10, 12, 13, 14, 15};
        x[xb + slot[tid]] = wred[tid][0] + wred[tid][1] + wred[tid][2] + wred[tid][3];
    }
    if (tid == 0) {
        x[xb + 0]  = rws[0][i];
        x[xb + 1]  = rws[1][i];
        x[xb + 2]  = rws[2][i];
        x[xb + 3]  = rws[3][i];
        x[xb + 7]  = cls[1][i];
        x[xb + 11] = cls[2][i];
    }
}

extern "C" void kernel_launch(void* const* d_in, const int* in_sizes, int n_in,
                              void* d_out, int out_size)
{
    const int*   code  = (const int*)d_in[0];
    const int*   pos   = (const int*)d_in[1];
    const void*  mask  = d_in[2];
    const float* table = (const float*)d_in[3];
    const float* W     = (const float*)d_in[4];
    const float* bias  = (const float*)d_in[5];
    float* out = (float*)d_out;

    float *pM1, *pM2, *pM3, *pM4, *pM8, *pM12, *px;
    __half *pxh, *pwt;
    cudaGetSymbolAddress((void**)&pM1,  g_M1);
    cudaGetSymbolAddress((void**)&pM2,  g_M2);
    cudaGetSymbolAddress((void**)&pM3,  g_M3);
    cudaGetSymbolAddress((void**)&pM4,  g_M4);
    cudaGetSymbolAddress((void**)&pM8,  g_M8);
    cudaGetSymbolAddress((void**)&pM12, g_M12);
    cudaGetSymbolAddress((void**)&px,   g_x);
    cudaGetSymbolAddress((void**)&pxh,  g_xh);
    cudaGetSymbolAddress((void**)&pwt,  g_wt);

    const long MS = (long)SEQ * SEQ;

    cudaFuncSetAttribute(gemm_final_fp16,
                         cudaFuncAttributeMaxDynamicSharedMemorySize, FSMEM);

    reset_flags_kernel<<<1, 1>>>();
    detect_mask_kernel<<<64, 256>>>((const uint4*)mask, in_sizes[2] / 16);

    dim3 gW(NPAD / 32, (KPAD + 31) / 32);
    convert_w_kernel<<<gW, 256>>>(W, pwt);

    embed_kernel<<<NROWS, 256>>>(code, pos, mask, table, px);
    build_m_kernel<<<NROWS, 128>>>(mask, pM1);

    dim3 gP(SEQ / 128, SEQ / 128, BATCH);
    dim3 gD(SEQ / 128, SEQ / 128, 2 * BATCH);
    gemm_tf32_kernel<<<gP, 256>>>(pM1, pM1, pM2, SEQ, MS);
    gemm_tf32_dual<<<gD, 256>>>(pM2, pM1, pM2, pM3, pM4, SEQ, MS);  // M3=M2*M1, M4=M2*M2
    gemm_tf32_kernel<<<gP, 256>>>(pM4, pM4, pM8,  SEQ, MS);
    gemm_tf32_kernel<<<gP, 256>>>(pM8, pM4, pM12, SEQ, MS);

    diag_pe_kernel<<<NROWS, 128>>>(pM1, pM2, pM3, pM4, pM8, pM12, px);

    convert_x_kernel<<<(NROWS * KPAD + 255) / 256, 256>>>(px, pxh);

    dim3 gF(NROWS / 128, NPAD / 128, 1);   // (16, 394)
    gemm_final_fp16<<<gF, 256, FSMEM>>>(pxh, pwt, out, bias);
}

// round 14
// speedup vs baseline: 1.1289x; 1.0108x over previous
#include <cuda_runtime.h>
#include <cuda_fp16.h>
#include <cstdint>

#define SEQ   512
#define BATCH 4
#define NROWS (BATCH * SEQ)
#define DEMB  768
#define DCAT  784
#define KPAD  832             // 13 chunks of 64 halves
#define KCHUNKS 13
#define VOCAB 50265
#define NPAD  50432           // 394 * 128
#define MSZ   (BATCH * SEQ * SEQ)

#define ACH 8192
#define BCH 8192

__device__ float  g_M1 [MSZ];
__device__ float  g_M2 [MSZ];
__device__ float  g_M3 [MSZ];
__device__ float  g_M4 [MSZ];
__device__ float  g_M8 [MSZ];
__device__ float  g_M12[MSZ];
__device__ __half g_xh[(size_t)(NROWS / 128) * KCHUNKS * ACH];
__device__ __half g_wt[(size_t)(NPAD / 128) * KCHUNKS * BCH];
__device__ int    g_mask_flags;

// ================= helpers =================
__device__ __forceinline__ uint32_t smem_u32(const void* p) {
    uint32_t a;
    asm("{ .reg .u64 t; cvta.to.shared.u64 t, %1; cvt.u32.u64 %0, t; }"
        : "=r"(a) : "l"(p));
    return a;
}
__device__ __host__ __forceinline__ uint32_t swz_half(int r, int kh) {
    return (uint32_t)(r * 64 + ((((kh >> 3) ^ r) & 7) << 3) + (kh & 7));
}
__device__ __forceinline__ void mbar_init(uint32_t a, uint32_t cnt) {
    asm volatile("mbarrier.init.shared.b64 [%0], %1;" :: "r"(a), "r"(cnt) : "memory");
}
__device__ __forceinline__ void mbar_expect_tx(uint32_t a, uint32_t bytes) {
    asm volatile("mbarrier.arrive.expect_tx.shared.b64 _, [%0], %1;"
                 :: "r"(a), "r"(bytes) : "memory");
}
__device__ __forceinline__ void mbar_arrive(uint32_t a) {
    asm volatile("mbarrier.arrive.shared.b64 _, [%0];" :: "r"(a) : "memory");
}
__device__ __forceinline__ void bulk_g2s(uint32_t dst, const void* src,
                                         uint32_t bytes, uint32_t mbar) {
    asm volatile(
        "cp.async.bulk.shared::cluster.global.mbarrier::complete_tx::bytes "
        "[%0], [%1], %2, [%3];"
        :: "r"(dst), "l"(src), "r"(bytes), "r"(mbar) : "memory");
}
__device__ __forceinline__ void mbar_wait(uint32_t a, uint32_t ph) {
    uint32_t done;
    asm volatile(
        "{\n\t.reg .pred p;\n\t"
        "mbarrier.try_wait.parity.acquire.cta.shared::cta.b64 p, [%1], %2;\n\t"
        "selp.b32 %0, 1, 0, p;\n\t}"
        : "=r"(done) : "r"(a), "r"(ph) : "memory");
    if (!done) {
        asm volatile(
            "{\n\t.reg .pred P1;\n\t"
            "WL_%=:\n\t"
            "mbarrier.try_wait.parity.acquire.cta.shared::cta.b64 P1, [%0], %1, 0x989680;\n\t"
            "@P1 bra.uni WD_%=;\n\t"
            "bra.uni WL_%=;\n\t"
            "WD_%=:\n\t}"
            :: "r"(a), "r"(ph) : "memory");
    }
}

// ================= mask dtype detection =================
__global__ void reset_flags_kernel() { g_mask_flags = 0; }

__global__ __launch_bounds__(256) void detect_mask_kernel(
    const uint4* __restrict__ p, int nvec)
{
    int fl = 0;
    for (int i = blockIdx.x * blockDim.x + threadIdx.x; i < nvec;
         i += gridDim.x * blockDim.x) {
        uint4 v = p[i];
        uint32_t any = v.x | v.y | v.z | v.w;
        if (any & 0xFEFEFEFEu) fl |= 2;
        else if (any & 0x01010100u) fl |= 1;
    }
    if (fl) atomicOr(&g_mask_flags, fl);
}

__device__ __forceinline__ int mask_fmt() {
    int f = g_mask_flags;
    return (f & 2) ? 2 : ((f & 1) ? 1 : 0);
}
__device__ __forceinline__ bool mask_at(const void* m, int fmt, long idx) {
    if (fmt == 0) return ((const int*)m)[idx] != 0;
    if (fmt == 1) return ((const unsigned char*)m)[idx] != 0;
    return ((const float*)m)[idx] != 0.0f;
}

// ================= W -> chunked swizzled fp16 (128-row tiles) =================
__global__ __launch_bounds__(256) void convert_w_kernel(
    const float* __restrict__ W, __half* __restrict__ Wt)
{
    __shared__ float t[32][33];
    int n0 = blockIdx.x * 32, k0 = blockIdx.y * 32;
    int tx = threadIdx.x & 31, ty = threadIdx.x >> 5;
    #pragma unroll
    for (int i = 0; i < 32; i += 8) {
        int k = k0 + ty + i, n = n0 + tx;
        t[ty + i][tx] = (k < DCAT && n < VOCAB) ? W[(size_t)k * VOCAB + n] : 0.0f;
    }
    __syncthreads();
    #pragma unroll
    for (int i = 0; i < 32; i += 8) {
        int n = n0 + ty + i, k = k0 + tx;
        int ntile = n >> 7, rr = n & 127;
        int kc = k >> 6, kh = k & 63;
        size_t base = ((size_t)ntile * KCHUNKS + kc) * BCH;
        Wt[base + swz_half(rr, kh)] = __float2half_rn(t[tx][ty + i]);
    }
}

// ================= embedding gather + node average -> swizzled fp16 xh =================
__global__ __launch_bounds__(256) void embed_kernel(
    const int* __restrict__ code, const int* __restrict__ pos,
    const void* __restrict__ mask, const float* __restrict__ table,
    __half* __restrict__ xh)
{
    int row = blockIdx.x;
    int b = row >> 9;
    int tid = threadIdx.x;
    int mtile = row >> 7, r = row & 127;
    size_t mbase = (size_t)mtile * KCHUNKS * ACH;

    float v0, v1, v2;
    if (pos[row] != 0) {
        long co = (long)code[row] * DEMB;
        v0 = table[co + tid];
        v1 = table[co + tid + 256];
        v2 = table[co + tid + 512];
    } else {
        __shared__ int list[SEQ];
        __shared__ int cnt;
        if (tid == 0) cnt = 0;
        __syncthreads();
        int fmt = mask_fmt();
        for (int j = tid; j < SEQ; j += 256) {
            bool f = (pos[(b << 9) + j] >= 2) && mask_at(mask, fmt, (long)row * SEQ + j);
            if (f) { int k = atomicAdd(&cnt, 1); list[k] = code[(b << 9) + j]; }
        }
        __syncthreads();
        int n = cnt;
        float inv = 1.0f / ((float)n + 1e-10f);
        float a0 = 0.f, a1 = 0.f, a2 = 0.f;
        int jj = 0;
        for (; jj + 4 <= n; jj += 4) {
            const float* e0 = table + (long)list[jj] * DEMB;
            const float* e1 = table + (long)list[jj + 1] * DEMB;
            const float* e2 = table + (long)list[jj + 2] * DEMB;
            const float* e3 = table + (long)list[jj + 3] * DEMB;
            a0 += e0[tid] + e1[tid] + e2[tid] + e3[tid];
            a1 += e0[tid + 256] + e1[tid + 256] + e2[tid + 256] + e3[tid + 256];
            a2 += e0[tid + 512] + e1[tid + 512] + e2[tid + 512] + e3[tid + 512];
        }
        for (; jj < n; jj++) {
            const float* e0 = table + (long)list[jj] * DEMB;
            a0 += e0[tid]; a1 += e0[tid + 256]; a2 += e0[tid + 512];
        }
        v0 = a0 * inv; v1 = a1 * inv; v2 = a2 * inv;
    }
    float vals[3] = {v0, v1, v2};
    #pragma unroll
    for (int l = 0; l < 3; l++) {
        int d = tid + l * 256;
        int kc = d >> 6, kh = d & 63;
        xh[mbase + (size_t)kc * ACH + swz_half(r, kh)] = __float2half_rn(vals[l]);
    }
}

// ================= M = D^-1 A =================
__global__ __launch_bounds__(128) void build_m_kernel(
    const void* __restrict__ mask, float* __restrict__ M1)
{
    int row = blockIdx.x;
    int i = row & (SEQ - 1);
    int tid = threadIdx.x;
    int fmt = mask_fmt();
    long base = (long)row * SEQ;
    __shared__ float red[128];

    float s = 0.f;
    for (int j = tid; j < SEQ; j += 128)
        s += (j == i) ? 1.0f : (mask_at(mask, fmt, base + j) ? 1.0f : 0.0f);
    red[tid] = s;
    __syncthreads();
    #pragma unroll
    for (int off = 64; off > 0; off >>= 1) {
        if (tid < off) red[tid] += red[tid + off];
        __syncthreads();
    }
    float inv = 1.0f / red[0];
    for (int j = tid; j < SEQ; j += 128) {
        float a = (j == i) ? 1.0f : (mask_at(mask, fmt, base + j) ? 1.0f : 0.0f);
        M1[base + j] = a * inv;
    }
}

__device__ __forceinline__ uint32_t f2tf32(float f) {
    uint32_t u;
    asm("cvt.rna.tf32.f32 %0, %1;" : "=r"(u) : "f"(f));
    return u;
}

// ================= power GEMM body (tf32 128x128) =================
__device__ __forceinline__ void gemm_tf32_body(
    const float* __restrict__ A, const float* __restrict__ B,
    float* __restrict__ C, int m0, int n0, int K)
{
    __shared__ float As[2][128][20];
    __shared__ float Bs[2][16][136];

    const int tid = threadIdx.x;
    const int lane = tid & 31, warp = tid >> 5;
    const int wm = (warp >> 2) * 64;
    const int wn = (warp & 3) * 32;
    const int g = lane >> 2, t4 = lane & 3;

    float acc[4][4][4];
    #pragma unroll
    for (int a = 0; a < 4; a++)
        #pragma unroll
        for (int bq = 0; bq < 4; bq++)
            #pragma unroll
            for (int c = 0; c < 4; c++) acc[a][bq][c] = 0.f;

    const int KT = K >> 4;
    float4 ra[2];
    float  rb[8];

    auto ldg_tiles = [&](int kt) {
        #pragma unroll
        for (int l = 0; l < 2; l++) {
            int idx = tid + l * 256;
            int ar = idx >> 2, ak = (idx & 3) << 2;
            ra[l] = *reinterpret_cast<const float4*>(
                A + (size_t)(m0 + ar) * SEQ + (kt * 16 + ak));
        }
        #pragma unroll
        for (int l = 0; l < 8; l++) {
            int idx = tid + l * 256;
            rb[l] = B[(size_t)(kt * 16 + (idx >> 7)) * SEQ + n0 + (idx & 127)];
        }
    };
    auto sts_tiles = [&](int buf) {
        #pragma unroll
        for (int l = 0; l < 2; l++) {
            int idx = tid + l * 256;
            int ar = idx >> 2, ak = (idx & 3) << 2;
            As[buf][ar][ak + 0] = __uint_as_float(f2tf32(ra[l].x));
            As[buf][ar][ak + 1] = __uint_as_float(f2tf32(ra[l].y));
            As[buf][ar][ak + 2] = __uint_as_float(f2tf32(ra[l].z));
            As[buf][ar][ak + 3] = __uint_as_float(f2tf32(ra[l].w));
        }
        #pragma unroll
        for (int l = 0; l < 8; l++) {
            int idx = tid + l * 256;
            Bs[buf][idx >> 7][idx & 127] = __uint_as_float(f2tf32(rb[l]));
        }
    };
    auto compute = [&](int buf) {
        #pragma unroll
        for (int ks = 0; ks < 2; ks++) {
            uint32_t af[4][4];
            int k = ks * 8 + t4;
            #pragma unroll
            for (int tm = 0; tm < 4; tm++) {
                int r = wm + tm * 16 + g;
                af[tm][0] = __float_as_uint(As[buf][r][k]);
                af[tm][1] = __float_as_uint(As[buf][r + 8][k]);
                af[tm][2] = __float_as_uint(As[buf][r][k + 4]);
                af[tm][3] = __float_as_uint(As[buf][r + 8][k + 4]);
            }
            uint32_t bf[4][2];
            #pragma unroll
            for (int tn = 0; tn < 4; tn++) {
                int c = wn + tn * 8 + g;
                bf[tn][0] = __float_as_uint(Bs[buf][k][c]);
                bf[tn][1] = __float_as_uint(Bs[buf][k + 4][c]);
            }
            #pragma unroll
            for (int tm = 0; tm < 4; tm++)
                #pragma unroll
                for (int tn = 0; tn < 4; tn++)
                    asm volatile(
                        "mma.sync.aligned.m16n8k8.row.col.f32.tf32.tf32.f32 "
                        "{%0,%1,%2,%3}, {%4,%5,%6,%7}, {%8,%9}, {%0,%1,%2,%3};\n"
                        : "+f"(acc[tm][tn][0]), "+f"(acc[tm][tn][1]),
                          "+f"(acc[tm][tn][2]), "+f"(acc[tm][tn][3])
                        : "r"(af[tm][0]), "r"(af[tm][1]),
                          "r"(af[tm][2]), "r"(af[tm][3]),
                          "r"(bf[tn][0]), "r"(bf[tn][1]));
        }
    };

    ldg_tiles(0);
    sts_tiles(0);
    __syncthreads();
    for (int kt = 0; kt < KT; kt++) {
        if (kt + 1 < KT) ldg_tiles(kt + 1);
        compute(kt & 1);
        if (kt + 1 < KT) sts_tiles((kt + 1) & 1);
        __syncthreads();
    }

    #pragma unroll
    for (int tm = 0; tm < 4; tm++) {
        int r = m0 + wm + tm * 16 + g;
        #pragma unroll
        for (int tn = 0; tn < 4; tn++) {
            int c = n0 + wn + tn * 8 + (t4 << 1);
            C[(size_t)r * SEQ + c]           = acc[tm][tn][0];
            C[(size_t)r * SEQ + c + 1]       = acc[tm][tn][1];
            C[(size_t)(r + 8) * SEQ + c]     = acc[tm][tn][2];
            C[(size_t)(r + 8) * SEQ + c + 1] = acc[tm][tn][3];
        }
    }
}

__global__ __launch_bounds__(256, 2) void gemm_tf32_kernel(
    const float* __restrict__ A, const float* __restrict__ B,
    float* __restrict__ C, int K, long strideM)
{
    gemm_tf32_body(A + blockIdx.z * strideM, B + blockIdx.z * strideM,
                   C + blockIdx.z * strideM, blockIdx.x * 128, blockIdx.y * 128, K);
}

__global__ __launch_bounds__(256, 2) void gemm_tf32_dual(
    const float* __restrict__ A,
    const float* __restrict__ B0, const float* __restrict__ B1,
    float* __restrict__ C0, float* __restrict__ C1,
    int K, long strideM)
{
    int z = blockIdx.z;
    int bz = z & 3;
    const float* B = (z < 4) ? B0 : B1;
    float*       C = (z < 4) ? C0 : C1;
    gemm_tf32_body(A + bz * strideM, B + bz * strideM, C + bz * strideM,
                   blockIdx.x * 128, blockIdx.y * 128, K);
}

// ================= final GEMM: fp16 mma, 128x128 tile, 2 CTAs/SM =================
#define STG_BYTES (ACH * 2 + BCH * 2)   // 32768
#define NSTAGE 3
#define FSMEM (NSTAGE * STG_BYTES + 1024)

__global__ __launch_bounds__(256, 2) void gemm_final_fp16(
    const __half* __restrict__ A, const __half* __restrict__ B,
    float* __restrict__ C, const float* __restrict__ bias)
{
    extern __shared__ char dynsm[];
    __shared__ __align__(8) uint64_t s_full[NSTAGE];
    __shared__ __align__(8) uint64_t s_empty[NSTAGE];

    const int mt = blockIdx.x;
    const int nt = blockIdx.y;
    const int m0 = mt * 128;
    const int n0 = nt * 128;
    const int tid = threadIdx.x;
    const int lane = tid & 31, warp = tid >> 5;
    const int wm = (warp >> 2) * 64;
    const int wn = (warp & 3) * 32;
    const int g = lane >> 2, t4 = lane & 3;

    uint32_t raw_u = smem_u32(dynsm);
    uint32_t base_u = (raw_u + 1023u) & ~1023u;
    char* base_g = dynsm + (base_u - raw_u);

    const __half* Ach = A + (size_t)mt * KCHUNKS * ACH;
    const __half* Bch = B + (size_t)nt * KCHUNKS * BCH;

    uint32_t fullb[NSTAGE], emptyb[NSTAGE];
    #pragma unroll
    for (int s = 0; s < NSTAGE; s++) {
        fullb[s]  = smem_u32(&s_full[s]);
        emptyb[s] = smem_u32(&s_empty[s]);
    }

    if (tid == 0) {
        #pragma unroll
        for (int s = 0; s < NSTAGE; s++) {
            mbar_init(fullb[s], 1);
            mbar_init(emptyb[s], 8);
        }
    }
    __syncthreads();

    if (tid == 0) {
        #pragma unroll
        for (int s = 0; s < NSTAGE; s++) {
            mbar_expect_tx(fullb[s], STG_BYTES);
            bulk_g2s(base_u + s * STG_BYTES,           Ach + (size_t)s * ACH, ACH * 2, fullb[s]);
            bulk_g2s(base_u + s * STG_BYTES + ACH * 2, Bch + (size_t)s * BCH, BCH * 2, fullb[s]);
        }
    }

    float acc[4][4][4];
    #pragma unroll
    for (int a = 0; a < 4; a++)
        #pragma unroll
        for (int b = 0; b < 4; b++)
            #pragma unroll
            for (int c = 0; c < 4; c++) acc[a][b][c] = 0.f;

    int fph[NSTAGE] = {0, 0, 0};
    int eph[NSTAGE] = {0, 0, 0};

    for (int kc = 0; kc < KCHUNKS; kc++) {
        int s = kc % NSTAGE;
        mbar_wait(fullb[s], fph[s]);
        fph[s] ^= 1;

        const char* a0 = base_g + s * STG_BYTES;
        const char* b0 = a0 + ACH * 2;

        #pragma unroll
        for (int kk = 0; kk < 4; kk++) {
            int kh = kk * 16 + 2 * t4;
            uint32_t af[4][4];
            #pragma unroll
            for (int tm = 0; tm < 4; tm++) {
                int r = wm + tm * 16 + g;
                af[tm][0] = *(const uint32_t*)(a0 + swz_half(r,     kh)     * 2);
                af[tm][1] = *(const uint32_t*)(a0 + swz_half(r + 8, kh)     * 2);
                af[tm][2] = *(const uint32_t*)(a0 + swz_half(r,     kh + 8) * 2);
                af[tm][3] = *(const uint32_t*)(a0 + swz_half(r + 8, kh + 8) * 2);
            }
            uint32_t bf[4][2];
            #pragma unroll
            for (int tn = 0; tn < 4; tn++) {
                int c = wn + tn * 8 + g;
                bf[tn][0] = *(const uint32_t*)(b0 + swz_half(c, kh)     * 2);
                bf[tn][1] = *(const uint32_t*)(b0 + swz_half(c, kh + 8) * 2);
            }
            #pragma unroll
            for (int tm = 0; tm < 4; tm++)
                #pragma unroll
                for (int tn = 0; tn < 4; tn++)
                    asm volatile(
                        "mma.sync.aligned.m16n8k16.row.col.f32.f16.f16.f32 "
                        "{%0,%1,%2,%3}, {%4,%5,%6,%7}, {%8,%9}, {%0,%1,%2,%3};\n"
                        : "+f"(acc[tm][tn][0]), "+f"(acc[tm][tn][1]),
                          "+f"(acc[tm][tn][2]), "+f"(acc[tm][tn][3])
                        : "r"(af[tm][0]), "r"(af[tm][1]),
                          "r"(af[tm][2]), "r"(af[tm][3]),
                          "r"(bf[tn][0]), "r"(bf[tn][1]));
        }

        __syncwarp();
        if (lane == 0) mbar_arrive(emptyb[s]);

        if (tid == 0) {
            int nkc = kc + NSTAGE;
            if (nkc < KCHUNKS) {
                mbar_wait(emptyb[s], eph[s]);
                eph[s] ^= 1;
                mbar_expect_tx(fullb[s], STG_BYTES);
                bulk_g2s(base_u + s * STG_BYTES,           Ach + (size_t)nkc * ACH, ACH * 2, fullb[s]);
                bulk_g2s(base_u + s * STG_BYTES + ACH * 2, Bch + (size_t)nkc * BCH, BCH * 2, fullb[s]);
            }
        }
    }

    // ---- epilogue: scalar stores (VOCAB odd pitch) ----
    bool interior = (n0 + 128 <= VOCAB);
    #pragma unroll
    for (int tm = 0; tm < 4; tm++) {
        int r = m0 + wm + tm * 16 + g;
        float* C0 = C + (size_t)r * VOCAB;
        float* C1 = C + (size_t)(r + 8) * VOCAB;
        #pragma unroll
        for (int tn = 0; tn < 4; tn++) {
            int c = n0 + wn + tn * 8 + (t4 << 1);
            if (interior) {
                float b0 = bias[c], b1 = bias[c + 1];
                C0[c]     = acc[tm][tn][0] + b0;
                C0[c + 1] = acc[tm][tn][1] + b1;
                C1[c]     = acc[tm][tn][2] + b0;
                C1[c + 1] = acc[tm][tn][3] + b1;
            } else {
                if (c < VOCAB) {
                    float bv = bias[c];
                    C0[c] = acc[tm][tn][0] + bv;
                    C1[c] = acc[tm][tn][2] + bv;
                }
                if (c + 1 < VOCAB) {
                    float bv = bias[c + 1];
                    C0[c + 1] = acc[tm][tn][1] + bv;
                    C1[c + 1] = acc[tm][tn][3] + bv;
                }
            }
        }
    }
}

// ================= diag(M^k) -> swizzled fp16 xh (PE dims + pad) =================
__global__ __launch_bounds__(128) void diag_pe_kernel(
    const float* __restrict__ M1, const float* __restrict__ M2,
    const float* __restrict__ M3, const float* __restrict__ M4,
    const float* __restrict__ M8, const float* __restrict__ M12,
    __half* __restrict__ xh)
{
    int row = blockIdx.x;
    int b = row >> 9, i = row & (SEQ - 1);
    int tid = threadIdx.x, lane = tid & 31, warp = tid >> 5;
    long base = (long)row * SEQ;
    long mbq  = (long)b * SEQ * SEQ;
    int mtile = row >> 7, r = row & 127;
    // PE dims 768..831 live in chunk kc=12, kh = d-768
    size_t cbase = ((size_t)mtile * KCHUNKS + 12) * ACH;

    __shared__ float rws[4][SEQ];
    __shared__ float cls[3][SEQ];
    __shared__ float wred[10][4];

    for (int j = tid; j < SEQ; j += 128) {
        rws[0][j] = M1[base + j];
        rws[1][j] = M2[base + j];
        rws[2][j] = M3[base + j];
        rws[3][j] = M4[base + j];
        cls[0][j] = M4 [mbq + (long)j * SEQ + i];
        cls[1][j] = M8 [mbq + (long)j * SEQ + i];
        cls[2][j] = M12[mbq + (long)j * SEQ + i];
    }
    __syncthreads();

    float part[10];
    #pragma unroll
    for (int p = 0; p < 10; p++) part[p] = 0.f;
    for (int j = tid; j < SEQ; j += 128) {
        float a1 = rws[0][j], a2 = rws[1][j], a3 = rws[2][j], a4 = rws[3][j];
        float c4 = cls[0][j], c8 = cls[1][j], c12 = cls[2][j];
        part[0] += a1 * c4;   part[1] += a2 * c4;   part[2] += a3 * c4;
        part[3] += a1 * c8;   part[4] += a2 * c8;   part[5] += a3 * c8;
        part[6] += a1 * c12;  part[7] += a2 * c12;  part[8] += a3 * c12;
        part[9] += a4 * c12;
    }
    #pragma unroll
    for (int p = 0; p < 10; p++) {
        float v = part[p];
        #pragma unroll
        for (int off = 16; off > 0; off >>= 1) v += __shfl_down_sync(0xffffffffu, v, off);
        if (lane == 0) wred[p][warp] = v;
    }
    __syncthreads();

    if (tid < 10) {
        const int slot[10] = {4, 5, 6, 8, 9, 10, 12, 13, 14, 15};
        float v = wred[tid][0] + wred[tid][1] + wred[tid][2] + wred[tid][3];
        xh[cbase + swz_half(r, slot[tid])] = __float2half_rn(v);
    }
    if (tid == 0) {
        xh[cbase + swz_half(r, 0)]  = __float2half_rn(rws[0][i]);
        xh[cbase + swz_half(r, 1)]  = __float2half_rn(rws[1][i]);
        xh[cbase + swz_half(r, 2)]  = __float2half_rn(rws[2][i]);
        xh[cbase + swz_half(r, 3)]  = __float2half_rn(rws[3][i]);
        xh[cbase + swz_half(r, 7)]  = __float2half_rn(cls[1][i]);
        xh[cbase + swz_half(r, 11)] = __float2half_rn(cls[2][i]);
    }
    // zero-fill K padding (dims 784..831 -> kh 16..63)
    if (tid >= 16 && tid < 64)
        xh[cbase + swz_half(r, tid)] = __half(0.0f);
}

extern "C" void kernel_launch(void* const* d_in, const int* in_sizes, int n_in,
                              void* d_out, int out_size)
{
    const int*   code  = (const int*)d_in[0];
    const int*   pos   = (const int*)d_in[1];
    const void*  mask  = d_in[2];
    const float* table = (const float*)d_in[3];
    const float* W     = (const float*)d_in[4];
    const float* bias  = (const float*)d_in[5];
    float* out = (float*)d_out;

    float *pM1, *pM2, *pM3, *pM4, *pM8, *pM12;
    __half *pxh, *pwt;
    cudaGetSymbolAddress((void**)&pM1,  g_M1);
    cudaGetSymbolAddress((void**)&pM2,  g_M2);
    cudaGetSymbolAddress((void**)&pM3,  g_M3);
    cudaGetSymbolAddress((void**)&pM4,  g_M4);
    cudaGetSymbolAddress((void**)&pM8,  g_M8);
    cudaGetSymbolAddress((void**)&pM12, g_M12);
    cudaGetSymbolAddress((void**)&pxh,  g_xh);
    cudaGetSymbolAddress((void**)&pwt,  g_wt);

    const long MS = (long)SEQ * SEQ;

    // one-time handles (identical captured work every call)
    static cudaStream_t s_side = nullptr;
    static cudaEvent_t  ev_fork = nullptr, ev_join = nullptr;
    if (!s_side) {
        cudaStreamCreateWithFlags(&s_side, cudaStreamNonBlocking);
        cudaEventCreateWithFlags(&ev_fork, cudaEventDisableTiming);
        cudaEventCreateWithFlags(&ev_join, cudaEventDisableTiming);
        cudaFuncSetAttribute(gemm_final_fp16,
                             cudaFuncAttributeMaxDynamicSharedMemorySize, FSMEM);
    }

    // fork: convert_w on side stream, concurrent with mask/embed/power chain
    cudaEventRecord(ev_fork, 0);
    cudaStreamWaitEvent(s_side, ev_fork, 0);
    dim3 gW(NPAD / 32, (KPAD + 31) / 32);
    convert_w_kernel<<<gW, 256, 0, s_side>>>(W, pwt);
    cudaEventRecord(ev_join, s_side);

    reset_flags_kernel<<<1, 1>>>();
    detect_mask_kernel<<<64, 256>>>((const uint4*)mask, in_sizes[2] / 16);

    embed_kernel<<<NROWS, 256>>>(code, pos, mask, table, pxh);
    build_m_kernel<<<NROWS, 128>>>(mask, pM1);

    dim3 gP(SEQ / 128, SEQ / 128, BATCH);
    dim3 gD(SEQ / 128, SEQ / 128, 2 * BATCH);
    gemm_tf32_kernel<<<gP, 256>>>(pM1, pM1, pM2, SEQ, MS);
    gemm_tf32_dual<<<gD, 256>>>(pM2, pM1, pM2, pM3, pM4, SEQ, MS);  // M3=M2*M1, M4=M2*M2
    gemm_tf32_kernel<<<gP, 256>>>(pM4, pM4, pM8,  SEQ, MS);
    gemm_tf32_kernel<<<gP, 256>>>(pM8, pM4, pM12, SEQ, MS);

    diag_pe_kernel<<<NROWS, 128>>>(pM1, pM2, pM3, pM4, pM8, pM12, pxh);

    // join: final GEMM needs Wt from the side stream
    cudaStreamWaitEvent(0, ev_join, 0);

    dim3 gF(NROWS / 128, NPAD / 128, 1);   // (16, 394)
    gemm_final_fp16<<<gF, 256, FSMEM>>>(pxh, pwt, out, bias);
}

// round 15
// speedup vs baseline: 1.3517x; 1.1974x over previous
#include <cuda_runtime.h>
#include <cuda_fp16.h>
#include <cstdint>

#define SEQ   512
#define BATCH 4
#define NROWS (BATCH * SEQ)
#define DEMB  768
#define DCAT  784
#define KPAD  832             // 13 chunks of 64 halves
#define KCHUNKS 13
#define VOCAB 50265
#define NPAD  50432           // 394 * 128
#define MSZ   (BATCH * SEQ * SEQ)

#define ACH 8192
#define BCH 8192

__device__ float  g_M1 [MSZ];
__device__ float  g_M2 [MSZ];
__device__ float  g_M3 [MSZ];
__device__ float  g_M4 [MSZ];
__device__ float  g_M8 [MSZ];
__device__ float  g_M12[MSZ];
__device__ __half g_xh[(size_t)(NROWS / 128) * KCHUNKS * ACH];
__device__ __half g_wt[(size_t)(NPAD / 128) * KCHUNKS * BCH];
__device__ int    g_mask_flags;

// ================= helpers =================
__device__ __forceinline__ uint32_t smem_u32(const void* p) {
    uint32_t a;
    asm("{ .reg .u64 t; cvta.to.shared.u64 t, %1; cvt.u32.u64 %0, t; }"
        : "=r"(a) : "l"(p));
    return a;
}
__device__ __host__ __forceinline__ uint32_t swz_half(int r, int kh) {
    return (uint32_t)(r * 64 + ((((kh >> 3) ^ r) & 7) << 3) + (kh & 7));
}
__device__ __forceinline__ void mbar_init(uint32_t a, uint32_t cnt) {
    asm volatile("mbarrier.init.shared.b64 [%0], %1;" :: "r"(a), "r"(cnt) : "memory");
}
__device__ __forceinline__ void mbar_expect_tx(uint32_t a, uint32_t bytes) {
    asm volatile("mbarrier.arrive.expect_tx.shared.b64 _, [%0], %1;"
                 :: "r"(a), "r"(bytes) : "memory");
}
__device__ __forceinline__ void mbar_arrive(uint32_t a) {
    asm volatile("mbarrier.arrive.shared.b64 _, [%0];" :: "r"(a) : "memory");
}
__device__ __forceinline__ void bulk_g2s(uint32_t dst, const void* src,
                                         uint32_t bytes, uint32_t mbar) {
    asm volatile(
        "cp.async.bulk.shared::cluster.global.mbarrier::complete_tx::bytes "
        "[%0], [%1], %2, [%3];"
        :: "r"(dst), "l"(src), "r"(bytes), "r"(mbar) : "memory");
}
__device__ __forceinline__ void mbar_wait(uint32_t a, uint32_t ph) {
    uint32_t done;
    asm volatile(
        "{\n\t.reg .pred p;\n\t"
        "mbarrier.try_wait.parity.acquire.cta.shared::cta.b64 p, [%1], %2;\n\t"
        "selp.b32 %0, 1, 0, p;\n\t}"
        : "=r"(done) : "r"(a), "r"(ph) : "memory");
    if (!done) {
        asm volatile(
            "{\n\t.reg .pred P1;\n\t"
            "WL_%=:\n\t"
            "mbarrier.try_wait.parity.acquire.cta.shared::cta.b64 P1, [%0], %1, 0x989680;\n\t"
            "@P1 bra.uni WD_%=;\n\t"
            "bra.uni WL_%=;\n\t"
            "WD_%=:\n\t}"
            :: "r"(a), "r"(ph) : "memory");
    }
}

// ================= mask dtype detection =================
__global__ void reset_flags_kernel() { g_mask_flags = 0; }

__global__ __launch_bounds__(256) void detect_mask_kernel(
    const uint4* __restrict__ p, int nvec)
{
    int fl = 0;
    for (int i = blockIdx.x * blockDim.x + threadIdx.x; i < nvec;
         i += gridDim.x * blockDim.x) {
        uint4 v = p[i];
        uint32_t any = v.x | v.y | v.z | v.w;
        if (any & 0xFEFEFEFEu) fl |= 2;
        else if (any & 0x01010100u) fl |= 1;
    }
    if (fl) atomicOr(&g_mask_flags, fl);
}

__device__ __forceinline__ int mask_fmt() {
    int f = g_mask_flags;
    return (f & 2) ? 2 : ((f & 1) ? 1 : 0);
}
__device__ __forceinline__ bool mask_at(const void* m, int fmt, long idx) {
    if (fmt == 0) return ((const int*)m)[idx] != 0;
    if (fmt == 1) return ((const unsigned char*)m)[idx] != 0;
    return ((const float*)m)[idx] != 0.0f;
}

// ================= W -> chunked swizzled fp16 (128-row tiles) =================
__global__ __launch_bounds__(256) void convert_w_kernel(
    const float* __restrict__ W, __half* __restrict__ Wt)
{
    __shared__ float t[32][33];
    int n0 = blockIdx.x * 32, k0 = blockIdx.y * 32;
    int tx = threadIdx.x & 31, ty = threadIdx.x >> 5;
    #pragma unroll
    for (int i = 0; i < 32; i += 8) {
        int k = k0 + ty + i, n = n0 + tx;
        t[ty + i][tx] = (k < DCAT && n < VOCAB) ? W[(size_t)k * VOCAB + n] : 0.0f;
    }
    __syncthreads();
    #pragma unroll
    for (int i = 0; i < 32; i += 8) {
        int n = n0 + ty + i, k = k0 + tx;
        int ntile = n >> 7, rr = n & 127;
        int kc = k >> 6, kh = k & 63;
        size_t base = ((size_t)ntile * KCHUNKS + kc) * BCH;
        Wt[base + swz_half(rr, kh)] = __float2half_rn(t[tx][ty + i]);
    }
}

// ================= embedding gather + node average -> swizzled fp16 xh =================
__global__ __launch_bounds__(256) void embed_kernel(
    const int* __restrict__ code, const int* __restrict__ pos,
    const void* __restrict__ mask, const float* __restrict__ table,
    __half* __restrict__ xh)
{
    int row = blockIdx.x;
    int b = row >> 9;
    int tid = threadIdx.x;
    int mtile = row >> 7, r = row & 127;
    size_t mbase = (size_t)mtile * KCHUNKS * ACH;

    float v0, v1, v2;
    if (pos[row] != 0) {
        long co = (long)code[row] * DEMB;
        v0 = table[co + tid];
        v1 = table[co + tid + 256];
        v2 = table[co + tid + 512];
    } else {
        __shared__ int list[SEQ];
        __shared__ int cnt;
        if (tid == 0) cnt = 0;
        __syncthreads();
        int fmt = mask_fmt();
        for (int j = tid; j < SEQ; j += 256) {
            bool f = (pos[(b << 9) + j] >= 2) && mask_at(mask, fmt, (long)row * SEQ + j);
            if (f) { int k = atomicAdd(&cnt, 1); list[k] = code[(b << 9) + j]; }
        }
        __syncthreads();
        int n = cnt;
        float inv = 1.0f / ((float)n + 1e-10f);
        float a0 = 0.f, a1 = 0.f, a2 = 0.f;
        int jj = 0;
        for (; jj + 4 <= n; jj += 4) {
            const float* e0 = table + (long)list[jj] * DEMB;
            const float* e1 = table + (long)list[jj + 1] * DEMB;
            const float* e2 = table + (long)list[jj + 2] * DEMB;
            const float* e3 = table + (long)list[jj + 3] * DEMB;
            a0 += e0[tid] + e1[tid] + e2[tid] + e3[tid];
            a1 += e0[tid + 256] + e1[tid + 256] + e2[tid + 256] + e3[tid + 256];
            a2 += e0[tid + 512] + e1[tid + 512] + e2[tid + 512] + e3[tid + 512];
        }
        for (; jj < n; jj++) {
            const float* e0 = table + (long)list[jj] * DEMB;
            a0 += e0[tid]; a1 += e0[tid + 256]; a2 += e0[tid + 512];
        }
        v0 = a0 * inv; v1 = a1 * inv; v2 = a2 * inv;
    }
    float vals[3] = {v0, v1, v2};
    #pragma unroll
    for (int l = 0; l < 3; l++) {
        int d = tid + l * 256;
        int kc = d >> 6, kh = d & 63;
        xh[mbase + (size_t)kc * ACH + swz_half(r, kh)] = __float2half_rn(vals[l]);
    }
}

// ================= M = D^-1 A =================
__global__ __launch_bounds__(128) void build_m_kernel(
    const void* __restrict__ mask, float* __restrict__ M1)
{
    int row = blockIdx.x;
    int i = row & (SEQ - 1);
    int tid = threadIdx.x;
    int fmt = mask_fmt();
    long base = (long)row * SEQ;
    __shared__ float red[128];

    float s = 0.f;
    for (int j = tid; j < SEQ; j += 128)
        s += (j == i) ? 1.0f : (mask_at(mask, fmt, base + j) ? 1.0f : 0.0f);
    red[tid] = s;
    __syncthreads();
    #pragma unroll
    for (int off = 64; off > 0; off >>= 1) {
        if (tid < off) red[tid] += red[tid + off];
        __syncthreads();
    }
    float inv = 1.0f / red[0];
    for (int j = tid; j < SEQ; j += 128) {
        float a = (j == i) ? 1.0f : (mask_at(mask, fmt, base + j) ? 1.0f : 0.0f);
        M1[base + j] = a * inv;
    }
}

__device__ __forceinline__ uint32_t f2tf32(float f) {
    uint32_t u;
    asm("cvt.rna.tf32.f32 %0, %1;" : "=r"(u) : "f"(f));
    return u;
}

// ================= power GEMM body (tf32, MTILE x 128) =================
template<int MTILE>
__device__ __forceinline__ void gemm_tf32_body(
    const float* __restrict__ A, const float* __restrict__ B,
    float* __restrict__ C, int m0, int n0, int K)
{
    constexpr int TM = MTILE / 32;        // 4 (128) or 2 (64)
    __shared__ float As[2][MTILE][20];
    __shared__ float Bs[2][16][136];

    const int tid = threadIdx.x;
    const int lane = tid & 31, warp = tid >> 5;
    const int wm = (warp >> 2) * (MTILE / 2);
    const int wn = (warp & 3) * 32;
    const int g = lane >> 2, t4 = lane & 3;

    float acc[TM][4][4];
    #pragma unroll
    for (int a = 0; a < TM; a++)
        #pragma unroll
        for (int bq = 0; bq < 4; bq++)
            #pragma unroll
            for (int c = 0; c < 4; c++) acc[a][bq][c] = 0.f;

    const int KT = K >> 4;
    float4 ra[MTILE / 64];
    float  rb[8];

    auto ldg_tiles = [&](int kt) {
        #pragma unroll
        for (int l = 0; l < MTILE / 64; l++) {
            int idx = tid + l * 256;
            int ar = idx >> 2, ak = (idx & 3) << 2;
            ra[l] = *reinterpret_cast<const float4*>(
                A + (size_t)(m0 + ar) * SEQ + (kt * 16 + ak));
        }
        #pragma unroll
        for (int l = 0; l < 8; l++) {
            int idx = tid + l * 256;
            rb[l] = B[(size_t)(kt * 16 + (idx >> 7)) * SEQ + n0 + (idx & 127)];
        }
    };
    auto sts_tiles = [&](int buf) {
        #pragma unroll
        for (int l = 0; l < MTILE / 64; l++) {
            int idx = tid + l * 256;
            int ar = idx >> 2, ak = (idx & 3) << 2;
            As[buf][ar][ak + 0] = __uint_as_float(f2tf32(ra[l].x));
            As[buf][ar][ak + 1] = __uint_as_float(f2tf32(ra[l].y));
            As[buf][ar][ak + 2] = __uint_as_float(f2tf32(ra[l].z));
            As[buf][ar][ak + 3] = __uint_as_float(f2tf32(ra[l].w));
        }
        #pragma unroll
        for (int l = 0; l < 8; l++) {
            int idx = tid + l * 256;
            Bs[buf][idx >> 7][idx & 127] = __uint_as_float(f2tf32(rb[l]));
        }
    };
    auto compute = [&](int buf) {
        #pragma unroll
        for (int ks = 0; ks < 2; ks++) {
            uint32_t af[TM][4];
            int k = ks * 8 + t4;
            #pragma unroll
            for (int tm = 0; tm < TM; tm++) {
                int r = wm + tm * 16 + g;
                af[tm][0] = __float_as_uint(As[buf][r][k]);
                af[tm][1] = __float_as_uint(As[buf][r + 8][k]);
                af[tm][2] = __float_as_uint(As[buf][r][k + 4]);
                af[tm][3] = __float_as_uint(As[buf][r + 8][k + 4]);
            }
            uint32_t bf[4][2];
            #pragma unroll
            for (int tn = 0; tn < 4; tn++) {
                int c = wn + tn * 8 + g;
                bf[tn][0] = __float_as_uint(Bs[buf][k][c]);
                bf[tn][1] = __float_as_uint(Bs[buf][k + 4][c]);
            }
            #pragma unroll
            for (int tm = 0; tm < TM; tm++)
                #pragma unroll
                for (int tn = 0; tn < 4; tn++)
                    asm volatile(
                        "mma.sync.aligned.m16n8k8.row.col.f32.tf32.tf32.f32 "
                        "{%0,%1,%2,%3}, {%4,%5,%6,%7}, {%8,%9}, {%0,%1,%2,%3};\n"
                        : "+f"(acc[tm][tn][0]), "+f"(acc[tm][tn][1]),
                          "+f"(acc[tm][tn][2]), "+f"(acc[tm][tn][3])
                        : "r"(af[tm][0]), "r"(af[tm][1]),
                          "r"(af[tm][2]), "r"(af[tm][3]),
                          "r"(bf[tn][0]), "r"(bf[tn][1]));
        }
    };

    ldg_tiles(0);
    sts_tiles(0);
    __syncthreads();
    for (int kt = 0; kt < KT; kt++) {
        if (kt + 1 < KT) ldg_tiles(kt + 1);
        compute(kt & 1);
        if (kt + 1 < KT) sts_tiles((kt + 1) & 1);
        __syncthreads();
    }

    #pragma unroll
    for (int tm = 0; tm < TM; tm++) {
        int r = m0 + wm + tm * 16 + g;
        #pragma unroll
        for (int tn = 0; tn < 4; tn++) {
            int c = n0 + wn + tn * 8 + (t4 << 1);
            C[(size_t)r * SEQ + c]           = acc[tm][tn][0];
            C[(size_t)r * SEQ + c + 1]       = acc[tm][tn][1];
            C[(size_t)(r + 8) * SEQ + c]     = acc[tm][tn][2];
            C[(size_t)(r + 8) * SEQ + c + 1] = acc[tm][tn][3];
        }
    }
}

__global__ __launch_bounds__(256, 2) void gemm_tf32_kernel(
    const float* __restrict__ A, const float* __restrict__ B,
    float* __restrict__ C, int K, long strideM)
{
    gemm_tf32_body<64>(A + blockIdx.z * strideM, B + blockIdx.z * strideM,
                       C + blockIdx.z * strideM, blockIdx.x * 64, blockIdx.y * 128, K);
}

__global__ __launch_bounds__(256, 2) void gemm_tf32_dual(
    const float* __restrict__ A,
    const float* __restrict__ B0, const float* __restrict__ B1,
    float* __restrict__ C0, float* __restrict__ C1,
    int K, long strideM)
{
    int z = blockIdx.z;
    int bz = z & 3;
    const float* B = (z < 4) ? B0 : B1;
    float*       C = (z < 4) ? C0 : C1;
    gemm_tf32_body<64>(A + bz * strideM, B + bz * strideM, C + bz * strideM,
                       blockIdx.x * 64, blockIdx.y * 128, K);
}

// ================= final GEMM: fp16 mma + ldmatrix, 128x128, 2 CTAs/SM =================
#define STG_BYTES (ACH * 2 + BCH * 2)   // 32768
#define NSTAGE 3
#define FSMEM (NSTAGE * STG_BYTES + 1024)

__global__ __launch_bounds__(256, 2) void gemm_final_fp16(
    const __half* __restrict__ A, const __half* __restrict__ B,
    float* __restrict__ C, const float* __restrict__ bias)
{
    extern __shared__ char dynsm[];
    __shared__ __align__(8) uint64_t s_full[NSTAGE];
    __shared__ __align__(8) uint64_t s_empty[NSTAGE];

    const int mt = blockIdx.x;
    const int nt = blockIdx.y;
    const int m0 = mt * 128;
    const int n0 = nt * 128;
    const int tid = threadIdx.x;
    const int lane = tid & 31, warp = tid >> 5;
    const int wm = (warp >> 2) * 64;
    const int wn = (warp & 3) * 32;
    const int g = lane >> 2, t4 = lane & 3;

    uint32_t raw_u = smem_u32(dynsm);
    uint32_t base_u = (raw_u + 1023u) & ~1023u;

    const __half* Ach = A + (size_t)mt * KCHUNKS * ACH;
    const __half* Bch = B + (size_t)nt * KCHUNKS * BCH;

    uint32_t fullb[NSTAGE], emptyb[NSTAGE];
    #pragma unroll
    for (int s = 0; s < NSTAGE; s++) {
        fullb[s]  = smem_u32(&s_full[s]);
        emptyb[s] = smem_u32(&s_empty[s]);
    }

    if (tid == 0) {
        #pragma unroll
        for (int s = 0; s < NSTAGE; s++) {
            mbar_init(fullb[s], 1);
            mbar_init(emptyb[s], 8);
        }
    }
    __syncthreads();

    if (tid == 0) {
        #pragma unroll
        for (int s = 0; s < NSTAGE; s++) {
            mbar_expect_tx(fullb[s], STG_BYTES);
            bulk_g2s(base_u + s * STG_BYTES,           Ach + (size_t)s * ACH, ACH * 2, fullb[s]);
            bulk_g2s(base_u + s * STG_BYTES + ACH * 2, Bch + (size_t)s * BCH, BCH * 2, fullb[s]);
        }
    }

    float acc[4][4][4];
    #pragma unroll
    for (int a = 0; a < 4; a++)
        #pragma unroll
        for (int b = 0; b < 4; b++)
            #pragma unroll
            for (int c = 0; c < 4; c++) acc[a][b][c] = 0.f;

    int fph[NSTAGE] = {0, 0, 0};
    int eph[NSTAGE] = {0, 0, 0};

    // ldmatrix lane-address components (constant across chunks)
    const int lm  = lane >> 3;         // matrix index 0..3
    const int l7  = lane & 7;
    const int a_row_off = (lm & 1) * 8 + l7;   // + wm + tm*16
    const int a_k_off   = (lm >> 1) * 8;       // + k0
    const int b_tnl     = lm >> 1;             // 0..1 within pair
    const int b_khalf   = lm & 1;

    for (int kc = 0; kc < KCHUNKS; kc++) {
        int s = kc % NSTAGE;
        mbar_wait(fullb[s], fph[s]);
        fph[s] ^= 1;

        uint32_t sA_u = base_u + s * STG_BYTES;
        uint32_t sB_u = sA_u + ACH * 2;

        #pragma unroll
        for (int kk = 0; kk < 4; kk++) {
            int k0 = kk * 16;
            uint32_t af[4][4];
            #pragma unroll
            for (int tm = 0; tm < 4; tm++) {
                int row  = wm + tm * 16 + a_row_off;
                int kcol = k0 + a_k_off;
                uint32_t addr = sA_u + swz_half(row, kcol) * 2;
                asm volatile(
                    "ldmatrix.sync.aligned.m8n8.x4.shared.b16 {%0,%1,%2,%3}, [%4];"
                    : "=r"(af[tm][0]), "=r"(af[tm][1]),
                      "=r"(af[tm][2]), "=r"(af[tm][3])
                    : "r"(addr));
            }
            uint32_t bf[4][2];
            #pragma unroll
            for (int half = 0; half < 2; half++) {
                int n    = wn + half * 16 + b_tnl * 8 + l7;
                int kcol = k0 + b_khalf * 8;
                uint32_t addr = sB_u + swz_half(n, kcol) * 2;
                asm volatile(
                    "ldmatrix.sync.aligned.m8n8.x4.shared.b16 {%0,%1,%2,%3}, [%4];"
                    : "=r"(bf[2 * half][0]), "=r"(bf[2 * half][1]),
                      "=r"(bf[2 * half + 1][0]), "=r"(bf[2 * half + 1][1])
                    : "r"(addr));
            }
            #pragma unroll
            for (int tm = 0; tm < 4; tm++)
                #pragma unroll
                for (int tn = 0; tn < 4; tn++)
                    asm volatile(
                        "mma.sync.aligned.m16n8k16.row.col.f32.f16.f16.f32 "
                        "{%0,%1,%2,%3}, {%4,%5,%6,%7}, {%8,%9}, {%0,%1,%2,%3};\n"
                        : "+f"(acc[tm][tn][0]), "+f"(acc[tm][tn][1]),
                          "+f"(acc[tm][tn][2]), "+f"(acc[tm][tn][3])
                        : "r"(af[tm][0]), "r"(af[tm][1]),
                          "r"(af[tm][2]), "r"(af[tm][3]),
                          "r"(bf[tn][0]), "r"(bf[tn][1]));
        }

        __syncwarp();
        if (lane == 0) mbar_arrive(emptyb[s]);

        if (tid == 0) {
            int nkc = kc + NSTAGE;
            if (nkc < KCHUNKS) {
                mbar_wait(emptyb[s], eph[s]);
                eph[s] ^= 1;
                mbar_expect_tx(fullb[s], STG_BYTES);
                bulk_g2s(base_u + s * STG_BYTES,           Ach + (size_t)nkc * ACH, ACH * 2, fullb[s]);
                bulk_g2s(base_u + s * STG_BYTES + ACH * 2, Bch + (size_t)nkc * BCH, BCH * 2, fullb[s]);
            }
        }
    }

    // ---- epilogue: scalar stores (VOCAB odd pitch) ----
    bool interior = (n0 + 128 <= VOCAB);
    #pragma unroll
    for (int tm = 0; tm < 4; tm++) {
        int r = m0 + wm + tm * 16 + g;
        float* C0 = C + (size_t)r * VOCAB;
        float* C1 = C + (size_t)(r + 8) * VOCAB;
        #pragma unroll
        for (int tn = 0; tn < 4; tn++) {
            int c = n0 + wn + tn * 8 + (t4 << 1);
            if (interior) {
                float b0 = bias[c], b1 = bias[c + 1];
                C0[c]     = acc[tm][tn][0] + b0;
                C0[c + 1] = acc[tm][tn][1] + b1;
                C1[c]     = acc[tm][tn][2] + b0;
                C1[c + 1] = acc[tm][tn][3] + b1;
            } else {
                if (c < VOCAB) {
                    float bv = bias[c];
                    C0[c] = acc[tm][tn][0] + bv;
                    C1[c] = acc[tm][tn][2] + bv;
                }
                if (c + 1 < VOCAB) {
                    float bv = bias[c + 1];
                    C0[c + 1] = acc[tm][tn][1] + bv;
                    C1[c + 1] = acc[tm][tn][3] + bv;
                }
            }
        }
    }
}

// ================= diag(M^k) -> swizzled fp16 xh (PE dims + pad) =================
__global__ __launch_bounds__(128) void diag_pe_kernel(
    const float* __restrict__ M1, const float* __restrict__ M2,
    const float* __restrict__ M3, const float* __restrict__ M4,
    const float* __restrict__ M8, const float* __restrict__ M12,
    __half* __restrict__ xh)
{
    int row = blockIdx.x;
    int b = row >> 9, i = row & (SEQ - 1);
    int tid = threadIdx.x, lane = tid & 31, warp = tid >> 5;
    long base = (long)row * SEQ;
    long mbq  = (long)b * SEQ * SEQ;
    int mtile = row >> 7, r = row & 127;
    size_t cbase = ((size_t)mtile * KCHUNKS + 12) * ACH;

    __shared__ float rws[4][SEQ];
    __shared__ float cls[3][SEQ];
    __shared__ float wred[10][4];

    for (int j = tid; j < SEQ; j += 128) {
        rws[0][j] = M1[base + j];
        rws[1][j] = M2[base + j];
        rws[2][j] = M3[base + j];
        rws[3][j] = M4[base + j];
        cls[0][j] = M4 [mbq + (long)j * SEQ + i];
        cls[1][j] = M8 [mbq + (long)j * SEQ + i];
        cls[2][j] = M12[mbq + (long)j * SEQ + i];
    }
    __syncthreads();

    float part[10];
    #pragma unroll
    for (int p = 0; p < 10; p++) part[p] = 0.f;
    for (int j = tid; j < SEQ; j += 128) {
        float a1 = rws[0][j], a2 = rws[1][j], a3 = rws[2][j], a4 = rws[3][j];
        float c4 = cls[0][j], c8 = cls[1][j], c12 = cls[2][j];
        part[0] += a1 * c4;   part[1] += a2 * c4;   part[2] += a3 * c4;
        part[3] += a1 * c8;   part[4] += a2 * c8;   part[5] += a3 * c8;
        part[6] += a1 * c12;  part[7] += a2 * c12;  part[8] += a3 * c12;
        part[9] += a4 * c12;
    }
    #pragma unroll
    for (int p = 0; p < 10; p++) {
        float v = part[p];
        #pragma unroll
        for (int off = 16; off > 0; off >>= 1) v += __shfl_down_sync(0xffffffffu, v, off);
        if (lane == 0) wred[p][warp] = v;
    }
    __syncthreads();

    if (tid < 10) {
        const int slot[10] = {4, 5, 6, 8, 9, 10, 12, 13, 14, 15};
        float v = wred[tid][0] + wred[tid][1] + wred[tid][2] + wred[tid][3];
        xh[cbase + swz_half(r, slot[tid])] = __float2half_rn(v);
    }
    if (tid == 0) {
        xh[cbase + swz_half(r, 0)]  = __float2half_rn(rws[0][i]);
        xh[cbase + swz_half(r, 1)]  = __float2half_rn(rws[1][i]);
        xh[cbase + swz_half(r, 2)]  = __float2half_rn(rws[2][i]);
        xh[cbase + swz_half(r, 3)]  = __float2half_rn(rws[3][i]);
        xh[cbase + swz_half(r, 7)]  = __float2half_rn(cls[1][i]);
        xh[cbase + swz_half(r, 11)] = __float2half_rn(cls[2][i]);
    }
    if (tid >= 16 && tid < 64)
        xh[cbase + swz_half(r, tid)] = __half(0.0f);
}

extern "C" void kernel_launch(void* const* d_in, const int* in_sizes, int n_in,
                              void* d_out, int out_size)
{
    const int*   code  = (const int*)d_in[0];
    const int*   pos   = (const int*)d_in[1];
    const void*  mask  = d_in[2];
    const float* table = (const float*)d_in[3];
    const float* W     = (const float*)d_in[4];
    const float* bias  = (const float*)d_in[5];
    float* out = (float*)d_out;

    float *pM1, *pM2, *pM3, *pM4, *pM8, *pM12;
    __half *pxh, *pwt;
    cudaGetSymbolAddress((void**)&pM1,  g_M1);
    cudaGetSymbolAddress((void**)&pM2,  g_M2);
    cudaGetSymbolAddress((void**)&pM3,  g_M3);
    cudaGetSymbolAddress((void**)&pM4,  g_M4);
    cudaGetSymbolAddress((void**)&pM8,  g_M8);
    cudaGetSymbolAddress((void**)&pM12, g_M12);
    cudaGetSymbolAddress((void**)&pxh,  g_xh);
    cudaGetSymbolAddress((void**)&pwt,  g_wt);

    const long MS = (long)SEQ * SEQ;

    static cudaStream_t s_side = nullptr;
    static cudaEvent_t  ev_fork = nullptr, ev_join = nullptr;
    if (!s_side) {
        cudaStreamCreateWithFlags(&s_side, cudaStreamNonBlocking);
        cudaEventCreateWithFlags(&ev_fork, cudaEventDisableTiming);
        cudaEventCreateWithFlags(&ev_join, cudaEventDisableTiming);
        cudaFuncSetAttribute(gemm_final_fp16,
                             cudaFuncAttributeMaxDynamicSharedMemorySize, FSMEM);
    }

    cudaEventRecord(ev_fork, 0);
    cudaStreamWaitEvent(s_side, ev_fork, 0);
    dim3 gW(NPAD / 32, (KPAD + 31) / 32);
    convert_w_kernel<<<gW, 256, 0, s_side>>>(W, pwt);
    cudaEventRecord(ev_join, s_side);

    reset_flags_kernel<<<1, 1>>>();
    detect_mask_kernel<<<64, 256>>>((const uint4*)mask, in_sizes[2] / 16);

    embed_kernel<<<NROWS, 256>>>(code, pos, mask, table, pxh);
    build_m_kernel<<<NROWS, 128>>>(mask, pM1);

    dim3 gP(SEQ / 64, SEQ / 128, BATCH);        // (8,4,4) = 128 CTAs
    dim3 gD(SEQ / 64, SEQ / 128, 2 * BATCH);    // (8,4,8) = 256 CTAs
    gemm_tf32_kernel<<<gP, 256>>>(pM1, pM1, pM2, SEQ, MS);
    gemm_tf32_dual<<<gD, 256>>>(pM2, pM1, pM2, pM3, pM4, SEQ, MS);  // M3=M2*M1, M4=M2*M2
    gemm_tf32_kernel<<<gP, 256>>>(pM4, pM4, pM8,  SEQ, MS);
    gemm_tf32_kernel<<<gP, 256>>>(pM8, pM4, pM12, SEQ, MS);

    diag_pe_kernel<<<NROWS, 128>>>(pM1, pM2, pM3, pM4, pM8, pM12, pxh);

    cudaStreamWaitEvent(0, ev_join, 0);

    dim3 gF(NROWS / 128, NPAD / 128, 1);   // (16, 394)
    gemm_final_fp16<<<gF, 256, FSMEM>>>(pxh, pwt, out, bias);
}

// round 16
// speedup vs baseline: 1.3940x; 1.0313x over previous
#include <cuda_runtime.h>
#include <cuda_fp16.h>
#include <cstdint>

#define SEQ   512
#define BATCH 4
#define NROWS (BATCH * SEQ)
#define DEMB  768
#define DCAT  784
#define KPAD  832             // 13 chunks of 64 halves
#define KCHUNKS 13
#define VOCAB 50265
#define NPAD  50432           // 394 * 128
#define MSZ   (BATCH * SEQ * SEQ)

#define ACH 8192
#define BCH 8192
#define PGRID 256

__device__ float  g_M1 [MSZ];
__device__ float  g_M2 [MSZ];
__device__ float  g_M3 [MSZ];
__device__ float  g_M4 [MSZ];
__device__ float  g_M8 [MSZ];
__device__ float  g_M12[MSZ];
__device__ __half g_xh[(size_t)(NROWS / 128) * KCHUNKS * ACH];
__device__ __half g_wt[(size_t)(NPAD / 128) * KCHUNKS * BCH];
__device__ int    g_mask_flags;
__device__ unsigned g_epoch  = 0;
__device__ unsigned g_bcount = 0;

// ================= helpers =================
__device__ __forceinline__ uint32_t smem_u32(const void* p) {
    uint32_t a;
    asm("{ .reg .u64 t; cvta.to.shared.u64 t, %1; cvt.u32.u64 %0, t; }"
        : "=r"(a) : "l"(p));
    return a;
}
__device__ __host__ __forceinline__ uint32_t swz_half(int r, int kh) {
    return (uint32_t)(r * 64 + ((((kh >> 3) ^ r) & 7) << 3) + (kh & 7));
}
__device__ __forceinline__ void mbar_init(uint32_t a, uint32_t cnt) {
    asm volatile("mbarrier.init.shared.b64 [%0], %1;" :: "r"(a), "r"(cnt) : "memory");
}
__device__ __forceinline__ void mbar_expect_tx(uint32_t a, uint32_t bytes) {
    asm volatile("mbarrier.arrive.expect_tx.shared.b64 _, [%0], %1;"
                 :: "r"(a), "r"(bytes) : "memory");
}
__device__ __forceinline__ void mbar_arrive(uint32_t a) {
    asm volatile("mbarrier.arrive.shared.b64 _, [%0];" :: "r"(a) : "memory");
}
__device__ __forceinline__ void bulk_g2s(uint32_t dst, const void* src,
                                         uint32_t bytes, uint32_t mbar) {
    asm volatile(
        "cp.async.bulk.shared::cluster.global.mbarrier::complete_tx::bytes "
        "[%0], [%1], %2, [%3];"
        :: "r"(dst), "l"(src), "r"(bytes), "r"(mbar) : "memory");
}
__device__ __forceinline__ void mbar_wait(uint32_t a, uint32_t ph) {
    uint32_t done;
    asm volatile(
        "{\n\t.reg .pred p;\n\t"
        "mbarrier.try_wait.parity.acquire.cta.shared::cta.b64 p, [%1], %2;\n\t"
        "selp.b32 %0, 1, 0, p;\n\t}"
        : "=r"(done) : "r"(a), "r"(ph) : "memory");
    if (!done) {
        asm volatile(
            "{\n\t.reg .pred P1;\n\t"
            "WL_%=:\n\t"
            "mbarrier.try_wait.parity.acquire.cta.shared::cta.b64 P1, [%0], %1, 0x989680;\n\t"
            "@P1 bra.uni WD_%=;\n\t"
            "bra.uni WL_%=;\n\t"
            "WD_%=:\n\t}"
            :: "r"(a), "r"(ph) : "memory");
    }
}
// grid barrier: epoch-based, replay-deterministic (epoch monotone)
__device__ __forceinline__ void gsync(unsigned base, int k) {
    __syncthreads();
    if (threadIdx.x == 0) {
        __threadfence();
        unsigned arrived = atomicAdd(&g_bcount, 1u);
        if (arrived == PGRID - 1) {
            g_bcount = 0;
            __threadfence();
            *(volatile unsigned*)&g_epoch = base + (unsigned)k;
        } else {
            while (*(volatile unsigned*)&g_epoch < base + (unsigned)k) __nanosleep(64);
        }
        __threadfence();
    }
    __syncthreads();
}

// ================= mask dtype detection =================
__global__ void reset_flags_kernel() { g_mask_flags = 0; }

__global__ __launch_bounds__(256) void detect_mask_kernel(
    const uint4* __restrict__ p, int nvec)
{
    int fl = 0;
    for (int i = blockIdx.x * blockDim.x + threadIdx.x; i < nvec;
         i += gridDim.x * blockDim.x) {
        uint4 v = p[i];
        uint32_t any = v.x | v.y | v.z | v.w;
        if (any & 0xFEFEFEFEu) fl |= 2;
        else if (any & 0x01010100u) fl |= 1;
    }
    if (fl) atomicOr(&g_mask_flags, fl);
}

__device__ __forceinline__ int mask_fmt() {
    int f = g_mask_flags;
    return (f & 2) ? 2 : ((f & 1) ? 1 : 0);
}
__device__ __forceinline__ bool mask_at(const void* m, int fmt, long idx) {
    if (fmt == 0) return ((const int*)m)[idx] != 0;
    if (fmt == 1) return ((const unsigned char*)m)[idx] != 0;
    return ((const float*)m)[idx] != 0.0f;
}

// ================= W -> chunked swizzled fp16 =================
__global__ __launch_bounds__(256) void convert_w_kernel(
    const float* __restrict__ W, __half* __restrict__ Wt)
{
    __shared__ float t[32][33];
    int n0 = blockIdx.x * 32, k0 = blockIdx.y * 32;
    int tx = threadIdx.x & 31, ty = threadIdx.x >> 5;
    #pragma unroll
    for (int i = 0; i < 32; i += 8) {
        int k = k0 + ty + i, n = n0 + tx;
        t[ty + i][tx] = (k < DCAT && n < VOCAB) ? W[(size_t)k * VOCAB + n] : 0.0f;
    }
    __syncthreads();
    #pragma unroll
    for (int i = 0; i < 32; i += 8) {
        int n = n0 + ty + i, k = k0 + tx;
        int ntile = n >> 7, rr = n & 127;
        int kc = k >> 6, kh = k & 63;
        size_t base = ((size_t)ntile * KCHUNKS + kc) * BCH;
        Wt[base + swz_half(rr, kh)] = __float2half_rn(t[tx][ty + i]);
    }
}

// ================= embedding gather + node average -> swizzled fp16 xh =================
__global__ __launch_bounds__(256) void embed_kernel(
    const int* __restrict__ code, const int* __restrict__ pos,
    const void* __restrict__ mask, const float* __restrict__ table,
    __half* __restrict__ xh)
{
    int row = blockIdx.x;
    int b = row >> 9;
    int tid = threadIdx.x;
    int mtile = row >> 7, r = row & 127;
    size_t mbase = (size_t)mtile * KCHUNKS * ACH;

    float v0, v1, v2;
    if (pos[row] != 0) {
        long co = (long)code[row] * DEMB;
        v0 = table[co + tid];
        v1 = table[co + tid + 256];
        v2 = table[co + tid + 512];
    } else {
        __shared__ int list[SEQ];
        __shared__ int cnt;
        if (tid == 0) cnt = 0;
        __syncthreads();
        int fmt = mask_fmt();
        for (int j = tid; j < SEQ; j += 256) {
            bool f = (pos[(b << 9) + j] >= 2) && mask_at(mask, fmt, (long)row * SEQ + j);
            if (f) { int k = atomicAdd(&cnt, 1); list[k] = code[(b << 9) + j]; }
        }
        __syncthreads();
        int n = cnt;
        float inv = 1.0f / ((float)n + 1e-10f);
        float a0 = 0.f, a1 = 0.f, a2 = 0.f;
        int jj = 0;
        for (; jj + 4 <= n; jj += 4) {
            const float* e0 = table + (long)list[jj] * DEMB;
            const float* e1 = table + (long)list[jj + 1] * DEMB;
            const float* e2 = table + (long)list[jj + 2] * DEMB;
            const float* e3 = table + (long)list[jj + 3] * DEMB;
            a0 += e0[tid] + e1[tid] + e2[tid] + e3[tid];
            a1 += e0[tid + 256] + e1[tid + 256] + e2[tid + 256] + e3[tid + 256];
            a2 += e0[tid + 512] + e1[tid + 512] + e2[tid + 512] + e3[tid + 512];
        }
        for (; jj < n; jj++) {
            const float* e0 = table + (long)list[jj] * DEMB;
            a0 += e0[tid]; a1 += e0[tid + 256]; a2 += e0[tid + 512];
        }
        v0 = a0 * inv; v1 = a1 * inv; v2 = a2 * inv;
    }
    float vals[3] = {v0, v1, v2};
    #pragma unroll
    for (int l = 0; l < 3; l++) {
        int d = tid + l * 256;
        int kc = d >> 6, kh = d & 63;
        xh[mbase + (size_t)kc * ACH + swz_half(r, kh)] = __float2half_rn(vals[l]);
    }
}

__device__ __forceinline__ uint32_t f2tf32(float f) {
    uint32_t u;
    asm("cvt.rna.tf32.f32 %0, %1;" : "=r"(u) : "f"(f));
    return u;
}

// ================= power-chain bodies (shared smem buffer) =================
// As: 2*64*20 = 2560 floats; Bs: 2*16*136 = 4352 floats; total 6912
#define SM_FLOATS 6912

__device__ void build_m_body(const void* mask, float* __restrict__ M1,
                             int row, float* red)
{
    int i = row & (SEQ - 1);
    int tid = threadIdx.x, lane = tid & 31, warp = tid >> 5;
    int fmt = mask_fmt();
    long base = (long)row * SEQ;

    float s = 0.f;
    for (int j = tid; j < SEQ; j += 256)
        s += (j == i) ? 1.0f : (mask_at(mask, fmt, base + j) ? 1.0f : 0.0f);
    #pragma unroll
    for (int off = 16; off > 0; off >>= 1) s += __shfl_down_sync(0xffffffffu, s, off);
    if (lane == 0) red[warp] = s;
    __syncthreads();
    float tot = red[0] + red[1] + red[2] + red[3] + red[4] + red[5] + red[6] + red[7];
    float inv = 1.0f / tot;
    for (int j = tid; j < SEQ; j += 256) {
        float a = (j == i) ? 1.0f : (mask_at(mask, fmt, base + j) ? 1.0f : 0.0f);
        M1[base + j] = a * inv;
    }
    __syncthreads();
}

__device__ void gemm64_body(const float* __restrict__ A, const float* __restrict__ B,
                            float* __restrict__ C, int m0, int n0,
                            float* As, float* Bs)   // As[2][64][20], Bs[2][16][136]
{
    const int tid = threadIdx.x;
    const int lane = tid & 31, warp = tid >> 5;
    const int wm = (warp >> 2) * 32;
    const int wn = (warp & 3) * 32;
    const int g = lane >> 2, t4 = lane & 3;

    float acc[2][4][4];
    #pragma unroll
    for (int a = 0; a < 2; a++)
        #pragma unroll
        for (int bq = 0; bq < 4; bq++)
            #pragma unroll
            for (int c = 0; c < 4; c++) acc[a][bq][c] = 0.f;

    const int KT = SEQ >> 4;   // 32
    float4 ra;
    float  rb[8];

    auto ldg_tiles = [&](int kt) {
        {
            int ar = tid >> 2, ak = (tid & 3) << 2;
            ra = *reinterpret_cast<const float4*>(
                A + (size_t)(m0 + ar) * SEQ + (kt * 16 + ak));
        }
        #pragma unroll
        for (int l = 0; l < 8; l++) {
            int idx = tid + l * 256;
            rb[l] = B[(size_t)(kt * 16 + (idx >> 7)) * SEQ + n0 + (idx & 127)];
        }
    };
    auto sts_tiles = [&](int buf) {
        {
            int ar = tid >> 2, ak = (tid & 3) << 2;
            float* dst = As + buf * 1280 + ar * 20 + ak;
            dst[0] = __uint_as_float(f2tf32(ra.x));
            dst[1] = __uint_as_float(f2tf32(ra.y));
            dst[2] = __uint_as_float(f2tf32(ra.z));
            dst[3] = __uint_as_float(f2tf32(ra.w));
        }
        #pragma unroll
        for (int l = 0; l < 8; l++) {
            int idx = tid + l * 256;
            Bs[buf * 2176 + (idx >> 7) * 136 + (idx & 127)] =
                __uint_as_float(f2tf32(rb[l]));
        }
    };
    auto compute = [&](int buf) {
        #pragma unroll
        for (int ks = 0; ks < 2; ks++) {
            uint32_t af[2][4];
            int k = ks * 8 + t4;
            #pragma unroll
            for (int tm = 0; tm < 2; tm++) {
                int r = wm + tm * 16 + g;
                const float* a0 = As + buf * 1280;
                af[tm][0] = __float_as_uint(a0[r * 20 + k]);
                af[tm][1] = __float_as_uint(a0[(r + 8) * 20 + k]);
                af[tm][2] = __float_as_uint(a0[r * 20 + k + 4]);
                af[tm][3] = __float_as_uint(a0[(r + 8) * 20 + k + 4]);
            }
            uint32_t bf[4][2];
            #pragma unroll
            for (int tn = 0; tn < 4; tn++) {
                int c = wn + tn * 8 + g;
                const float* b0 = Bs + buf * 2176;
                bf[tn][0] = __float_as_uint(b0[k * 136 + c]);
                bf[tn][1] = __float_as_uint(b0[(k + 4) * 136 + c]);
            }
            #pragma unroll
            for (int tm = 0; tm < 2; tm++)
                #pragma unroll
                for (int tn = 0; tn < 4; tn++)
                    asm volatile(
                        "mma.sync.aligned.m16n8k8.row.col.f32.tf32.tf32.f32 "
                        "{%0,%1,%2,%3}, {%4,%5,%6,%7}, {%8,%9}, {%0,%1,%2,%3};\n"
                        : "+f"(acc[tm][tn][0]), "+f"(acc[tm][tn][1]),
                          "+f"(acc[tm][tn][2]), "+f"(acc[tm][tn][3])
                        : "r"(af[tm][0]), "r"(af[tm][1]),
                          "r"(af[tm][2]), "r"(af[tm][3]),
                          "r"(bf[tn][0]), "r"(bf[tn][1]));
        }
    };

    ldg_tiles(0);
    sts_tiles(0);
    __syncthreads();
    for (int kt = 0; kt < KT; kt++) {
        if (kt + 1 < KT) ldg_tiles(kt + 1);
        compute(kt & 1);
        if (kt + 1 < KT) sts_tiles((kt + 1) & 1);
        __syncthreads();
    }

    #pragma unroll
    for (int tm = 0; tm < 2; tm++) {
        int r = m0 + wm + tm * 16 + g;
        #pragma unroll
        for (int tn = 0; tn < 4; tn++) {
            int c = n0 + wn + tn * 8 + (t4 << 1);
            C[(size_t)r * SEQ + c]           = acc[tm][tn][0];
            C[(size_t)r * SEQ + c + 1]       = acc[tm][tn][1];
            C[(size_t)(r + 8) * SEQ + c]     = acc[tm][tn][2];
            C[(size_t)(r + 8) * SEQ + c + 1] = acc[tm][tn][3];
        }
    }
    __syncthreads();
}

__device__ void diag_body(const float* __restrict__ M1, const float* __restrict__ M2,
                          const float* __restrict__ M3, const float* __restrict__ M4,
                          const float* __restrict__ M8, const float* __restrict__ M12,
                          __half* __restrict__ xh, int row, float* sm)
{
    int b = row >> 9, i = row & (SEQ - 1);
    int tid = threadIdx.x, lane = tid & 31, warp = tid >> 5;
    long base = (long)row * SEQ;
    long mbq  = (long)b * SEQ * SEQ;
    int mtile = row >> 7, r = row & 127;
    size_t cbase = ((size_t)mtile * KCHUNKS + 12) * ACH;

    // layout in sm: rws 4*512, cls 3*512, wred 10*8
    float* rws = sm;                 // [4][512]
    float* cls = sm + 4 * SEQ;       // [3][512]
    float* wred = sm + 7 * SEQ;      // [10][8]

    for (int j = tid; j < SEQ; j += 256) {
        rws[0 * SEQ + j] = M1[base + j];
        rws[1 * SEQ + j] = M2[base + j];
        rws[2 * SEQ + j] = M3[base + j];
        rws[3 * SEQ + j] = M4[base + j];
        cls[0 * SEQ + j] = M4 [mbq + (long)j * SEQ + i];
        cls[1 * SEQ + j] = M8 [mbq + (long)j * SEQ + i];
        cls[2 * SEQ + j] = M12[mbq + (long)j * SEQ + i];
    }
    __syncthreads();

    float part[10];
    #pragma unroll
    for (int p = 0; p < 10; p++) part[p] = 0.f;
    for (int j = tid; j < SEQ; j += 256) {
        float a1 = rws[j], a2 = rws[SEQ + j], a3 = rws[2 * SEQ + j], a4 = rws[3 * SEQ + j];
        float c4 = cls[j], c8 = cls[SEQ + j], c12 = cls[2 * SEQ + j];
        part[0] += a1 * c4;   part[1] += a2 * c4;   part[2] += a3 * c4;
        part[3] += a1 * c8;   part[4] += a2 * c8;   part[5] += a3 * c8;
        part[6] += a1 * c12;  part[7] += a2 * c12;  part[8] += a3 * c12;
        part[9] += a4 * c12;
    }
    #pragma unroll
    for (int p = 0; p < 10; p++) {
        float v = part[p];
        #pragma unroll
        for (int off = 16; off > 0; off >>= 1) v += __shfl_down_sync(0xffffffffu, v, off);
        if (lane == 0) wred[p * 8 + warp] = v;
    }
    __syncthreads();

    if (tid < 10) {
        const int slot[10] = {4, 5, 6, 8, 9, 10, 12, 13, 14, 15};
        float v = 0.f;
        #pragma unroll
        for (int w = 0; w < 8; w++) v += wred[tid * 8 + w];
        xh[cbase + swz_half(r, slot[tid])] = __float2half_rn(v);
    }
    if (tid == 0) {
        xh[cbase + swz_half(r, 0)]  = __float2half_rn(rws[i]);
        xh[cbase + swz_half(r, 1)]  = __float2half_rn(rws[SEQ + i]);
        xh[cbase + swz_half(r, 2)]  = __float2half_rn(rws[2 * SEQ + i]);
        xh[cbase + swz_half(r, 3)]  = __float2half_rn(rws[3 * SEQ + i]);
        xh[cbase + swz_half(r, 7)]  = __float2half_rn(cls[SEQ + i]);
        xh[cbase + swz_half(r, 11)] = __float2half_rn(cls[2 * SEQ + i]);
    }
    if (tid >= 16 && tid < 64)
        xh[cbase + swz_half(r, tid)] = __half(0.0f);
    __syncthreads();
}

// ================= fused persistent power chain =================
__global__ __launch_bounds__(256, 2) void power_chain_kernel(
    const void* __restrict__ mask,
    float* __restrict__ M1, float* __restrict__ M2, float* __restrict__ M3,
    float* __restrict__ M4, float* __restrict__ M8, float* __restrict__ M12,
    __half* __restrict__ xh)
{
    __shared__ float sm[SM_FLOATS];
    __shared__ unsigned s_base;
    float* As = sm;
    float* Bs = sm + 2560;
    const long MS = (long)SEQ * SEQ;

    if (threadIdx.x == 0) s_base = *(volatile unsigned*)&g_epoch;
    __syncthreads();
    unsigned base = s_base;

    // p0: build M1
    for (int row = blockIdx.x; row < NROWS; row += PGRID)
        build_m_body(mask, M1, row, sm);
    gsync(base, 1);

    // p1: M2 = M1*M1   (128 units: b(4) x mt(8) x nt(4))
    for (int u = blockIdx.x; u < 128; u += PGRID) {
        int b = u >> 5, t = u & 31, mt = t >> 2, nt = t & 3;
        gemm64_body(M1 + b * MS, M1 + b * MS, M2 + b * MS, mt * 64, nt * 128, As, Bs);
    }
    gsync(base, 2);

    // p2: M3 = M2*M1, M4 = M2*M2  (256 units)
    for (int u = blockIdx.x; u < 256; u += PGRID) {
        int op = u >> 7, rem = u & 127;
        int b = rem >> 5, t = rem & 31, mt = t >> 2, nt = t & 3;
        const float* Bp = op ? (M2 + b * MS) : (M1 + b * MS);
        float*       Cp = op ? (M4 + b * MS) : (M3 + b * MS);
        gemm64_body(M2 + b * MS, Bp, Cp, mt * 64, nt * 128, As, Bs);
    }
    gsync(base, 3);

    // p3: M8 = M4*M4
    for (int u = blockIdx.x; u < 128; u += PGRID) {
        int b = u >> 5, t = u & 31, mt = t >> 2, nt = t & 3;
        gemm64_body(M4 + b * MS, M4 + b * MS, M8 + b * MS, mt * 64, nt * 128, As, Bs);
    }
    gsync(base, 4);

    // p4: M12 = M8*M4
    for (int u = blockIdx.x; u < 128; u += PGRID) {
        int b = u >> 5, t = u & 31, mt = t >> 2, nt = t & 3;
        gemm64_body(M8 + b * MS, M4 + b * MS, M12 + b * MS, mt * 64, nt * 128, As, Bs);
    }
    gsync(base, 5);

    // p5: diag -> xh chunk 12
    for (int row = blockIdx.x; row < NROWS; row += PGRID)
        diag_body(M1, M2, M3, M4, M8, M12, xh, row, sm);
}

// ================= final GEMM: fp16 mma + ldmatrix, 128x128, 2 CTAs/SM =================
#define STG_BYTES (ACH * 2 + BCH * 2)   // 32768
#define NSTAGE 3
#define FSMEM (NSTAGE * STG_BYTES + 1024)

__global__ __launch_bounds__(256, 2) void gemm_final_fp16(
    const __half* __restrict__ A, const __half* __restrict__ B,
    float* __restrict__ C, const float* __restrict__ bias)
{
    extern __shared__ char dynsm[];
    __shared__ __align__(8) uint64_t s_full[NSTAGE];
    __shared__ __align__(8) uint64_t s_empty[NSTAGE];

    const int mt = blockIdx.x;
    const int nt = blockIdx.y;
    const int m0 = mt * 128;
    const int n0 = nt * 128;
    const int tid = threadIdx.x;
    const int lane = tid & 31, warp = tid >> 5;
    const int wm = (warp >> 2) * 64;
    const int wn = (warp & 3) * 32;
    const int g = lane >> 2, t4 = lane & 3;

    uint32_t raw_u = smem_u32(dynsm);
    uint32_t base_u = (raw_u + 1023u) & ~1023u;

    const __half* Ach = A + (size_t)mt * KCHUNKS * ACH;
    const __half* Bch = B + (size_t)nt * KCHUNKS * BCH;

    uint32_t fullb[NSTAGE], emptyb[NSTAGE];
    #pragma unroll
    for (int s = 0; s < NSTAGE; s++) {
        fullb[s]  = smem_u32(&s_full[s]);
        emptyb[s] = smem_u32(&s_empty[s]);
    }

    if (tid == 0) {
        #pragma unroll
        for (int s = 0; s < NSTAGE; s++) {
            mbar_init(fullb[s], 1);
            mbar_init(emptyb[s], 8);
        }
    }
    __syncthreads();

    if (tid == 0) {
        #pragma unroll
        for (int s = 0; s < NSTAGE; s++) {
            mbar_expect_tx(fullb[s], STG_BYTES);
            bulk_g2s(base_u + s * STG_BYTES,           Ach + (size_t)s * ACH, ACH * 2, fullb[s]);
            bulk_g2s(base_u + s * STG_BYTES + ACH * 2, Bch + (size_t)s * BCH, BCH * 2, fullb[s]);
        }
    }

    float acc[4][4][4];
    #pragma unroll
    for (int a = 0; a < 4; a++)
        #pragma unroll
        for (int b = 0; b < 4; b++)
            #pragma unroll
            for (int c = 0; c < 4; c++) acc[a][b][c] = 0.f;

    int fph[NSTAGE] = {0, 0, 0};
    int eph[NSTAGE] = {0, 0, 0};

    const int lm  = lane >> 3;
    const int l7  = lane & 7;
    const int a_row_off = (lm & 1) * 8 + l7;
    const int a_k_off   = (lm >> 1) * 8;
    const int b_tnl     = lm >> 1;
    const int b_khalf   = lm & 1;

    for (int kc = 0; kc < KCHUNKS; kc++) {
        int s = kc % NSTAGE;
        mbar_wait(fullb[s], fph[s]);
        fph[s] ^= 1;

        uint32_t sA_u = base_u + s * STG_BYTES;
        uint32_t sB_u = sA_u + ACH * 2;

        #pragma unroll
        for (int kk = 0; kk < 4; kk++) {
            int k0 = kk * 16;
            uint32_t af[4][4];
            #pragma unroll
            for (int tm = 0; tm < 4; tm++) {
                int row  = wm + tm * 16 + a_row_off;
                int kcol = k0 + a_k_off;
                uint32_t addr = sA_u + swz_half(row, kcol) * 2;
                asm volatile(
                    "ldmatrix.sync.aligned.m8n8.x4.shared.b16 {%0,%1,%2,%3}, [%4];"
                    : "=r"(af[tm][0]), "=r"(af[tm][1]),
                      "=r"(af[tm][2]), "=r"(af[tm][3])
                    : "r"(addr));
            }
            uint32_t bf[4][2];
            #pragma unroll
            for (int half = 0; half < 2; half++) {
                int n    = wn + half * 16 + b_tnl * 8 + l7;
                int kcol = k0 + b_khalf * 8;
                uint32_t addr = sB_u + swz_half(n, kcol) * 2;
                asm volatile(
                    "ldmatrix.sync.aligned.m8n8.x4.shared.b16 {%0,%1,%2,%3}, [%4];"
                    : "=r"(bf[2 * half][0]), "=r"(bf[2 * half][1]),
                      "=r"(bf[2 * half + 1][0]), "=r"(bf[2 * half + 1][1])
                    : "r"(addr));
            }
            #pragma unroll
            for (int tm = 0; tm < 4; tm++)
                #pragma unroll
                for (int tn = 0; tn < 4; tn++)
                    asm volatile(
                        "mma.sync.aligned.m16n8k16.row.col.f32.f16.f16.f32 "
                        "{%0,%1,%2,%3}, {%4,%5,%6,%7}, {%8,%9}, {%0,%1,%2,%3};\n"
                        : "+f"(acc[tm][tn][0]), "+f"(acc[tm][tn][1]),
                          "+f"(acc[tm][tn][2]), "+f"(acc[tm][tn][3])
                        : "r"(af[tm][0]), "r"(af[tm][1]),
                          "r"(af[tm][2]), "r"(af[tm][3]),
                          "r"(bf[tn][0]), "r"(bf[tn][1]));
        }

        __syncwarp();
        if (lane == 0) mbar_arrive(emptyb[s]);

        if (tid == 0) {
            int nkc = kc + NSTAGE;
            if (nkc < KCHUNKS) {
                mbar_wait(emptyb[s], eph[s]);
                eph[s] ^= 1;
                mbar_expect_tx(fullb[s], STG_BYTES);
                bulk_g2s(base_u + s * STG_BYTES,           Ach + (size_t)nkc * ACH, ACH * 2, fullb[s]);
                bulk_g2s(base_u + s * STG_BYTES + ACH * 2, Bch + (size_t)nkc * BCH, BCH * 2, fullb[s]);
            }
        }
    }

    bool interior = (n0 + 128 <= VOCAB);
    #pragma unroll
    for (int tm = 0; tm < 4; tm++) {
        int r = m0 + wm + tm * 16 + g;
        float* C0 = C + (size_t)r * VOCAB;
        float* C1 = C + (size_t)(r + 8) * VOCAB;
        #pragma unroll
        for (int tn = 0; tn < 4; tn++) {
            int c = n0 + wn + tn * 8 + (t4 << 1);
            if (interior) {
                float b0 = bias[c], b1 = bias[c + 1];
                C0[c]     = acc[tm][tn][0] + b0;
                C0[c + 1] = acc[tm][tn][1] + b1;
                C1[c]     = acc[tm][tn][2] + b0;
                C1[c + 1] = acc[tm][tn][3] + b1;
            } else {
                if (c < VOCAB) {
                    float bv = bias[c];
                    C0[c] = acc[tm][tn][0] + bv;
                    C1[c] = acc[tm][tn][2] + bv;
                }
                if (c + 1 < VOCAB) {
                    float bv = bias[c + 1];
                    C0[c + 1] = acc[tm][tn][1] + bv;
                    C1[c + 1] = acc[tm][tn][3] + bv;
                }
            }
        }
    }
}

extern "C" void kernel_launch(void* const* d_in, const int* in_sizes, int n_in,
                              void* d_out, int out_size)
{
    const int*   code  = (const int*)d_in[0];
    const int*   pos   = (const int*)d_in[1];
    const void*  mask  = d_in[2];
    const float* table = (const float*)d_in[3];
    const float* W     = (const float*)d_in[4];
    const float* bias  = (const float*)d_in[5];
    float* out = (float*)d_out;

    float *pM1, *pM2, *pM3, *pM4, *pM8, *pM12;
    __half *pxh, *pwt;
    cudaGetSymbolAddress((void**)&pM1,  g_M1);
    cudaGetSymbolAddress((void**)&pM2,  g_M2);
    cudaGetSymbolAddress((void**)&pM3,  g_M3);
    cudaGetSymbolAddress((void**)&pM4,  g_M4);
    cudaGetSymbolAddress((void**)&pM8,  g_M8);
    cudaGetSymbolAddress((void**)&pM12, g_M12);
    cudaGetSymbolAddress((void**)&pxh,  g_xh);
    cudaGetSymbolAddress((void**)&pwt,  g_wt);

    static cudaStream_t s_side = nullptr;
    static cudaEvent_t  ev_fork = nullptr, ev_det = nullptr, ev_side = nullptr;
    if (!s_side) {
        cudaStreamCreateWithFlags(&s_side, cudaStreamNonBlocking);
        cudaEventCreateWithFlags(&ev_fork, cudaEventDisableTiming);
        cudaEventCreateWithFlags(&ev_det,  cudaEventDisableTiming);
        cudaEventCreateWithFlags(&ev_side, cudaEventDisableTiming);
        cudaFuncSetAttribute(gemm_final_fp16,
                             cudaFuncAttributeMaxDynamicSharedMemorySize, FSMEM);
    }

    // fork at head: convert_w independent of everything
    cudaEventRecord(ev_fork, 0);
    cudaStreamWaitEvent(s_side, ev_fork, 0);
    dim3 gW(NPAD / 32, (KPAD + 31) / 32);
    convert_w_kernel<<<gW, 256, 0, s_side>>>(W, pwt);

    // main: mask dtype detection
    reset_flags_kernel<<<1, 1>>>();
    detect_mask_kernel<<<64, 256>>>((const uint4*)mask, in_sizes[2] / 16);
    cudaEventRecord(ev_det, 0);

    // side: embed (needs detect) runs concurrent with power chain
    cudaStreamWaitEvent(s_side, ev_det, 0);
    embed_kernel<<<NROWS, 256, 0, s_side>>>(code, pos, mask, table, pxh);
    cudaEventRecord(ev_side, s_side);

    // main: fused build_m + powers + diag (persistent, grid-barriered)
    power_chain_kernel<<<PGRID, 256>>>(mask, pM1, pM2, pM3, pM4, pM8, pM12, pxh);

    // join: final GEMM needs embed (xh chunks 0-11) and convert_w (Wt)
    cudaStreamWaitEvent(0, ev_side, 0);

    dim3 gF(NROWS / 128, NPAD / 128, 1);   // (16, 394)
    gemm_final_fp16<<<gF, 256, FSMEM>>>(pxh, pwt, out, bias);
}